// round 11
// baseline (speedup 1.0000x reference)
#include <cuda_runtime.h>

#define N_NODES 8192
#define C_DIM   16
#define NC_ITEMS (N_NODES * C_DIM)
#define R_ANCH  32
#define XD      224
#define NCHUNK  64
#define ESCALE  0.15811388300841898f

typedef unsigned long long ull;

__device__ float g_logits[NC_ITEMS * R_ANCH];
__device__ float g_pm[C_DIM * 16 * R_ANCH];
__device__ float g_ps[C_DIM * 16 * R_ANCH];
__device__ float g_part[NCHUNK * C_DIM * R_ANCH * XD];
__device__ float g_gbuf[R_ANCH * C_DIM * XD];
__device__ float g_ke[C_DIM * R_ANCH * XD];
__device__ float g_ve[C_DIM * R_ANCH * XD];
__device__ float g_q[(size_t)NC_ITEMS * XD];
__device__ float g_wqT[160 * 128];
__device__ float g_wpT[160 * 32];
__device__ float g_wsvT[128 * 32];

__device__ __forceinline__ float sigf(float x) { return 1.0f / (1.0f + __expf(-x)); }
#define FMA2(d, a, b) asm("fma.rn.f32x2 %0, %1, %2, %0;" : "+l"(d) : "l"(a), "l"(b))
__device__ __forceinline__ ull packx2(float x) {
    ull o; unsigned r = __float_as_uint(x);
    asm("mov.b64 %0, {%1, %1};" : "=l"(o) : "r"(r));
    return o;
}
__device__ __forceinline__ ull pack2(float a, float b) {
    ull o;
    asm("mov.b64 %0, {%1, %2};" : "=l"(o) : "f"(a), "f"(b));
    return o;
}
__device__ __forceinline__ float2 unpk(ull u) {
    float2 f;
    asm("mov.b64 {%0, %1}, %2;" : "=f"(f.x), "=f"(f.y) : "l"(u));
    return f;
}

// ---- k0: weight transposes ----
__global__ void k0_transpose(const float* __restrict__ qw, const float* __restrict__ pw,
                             const float* __restrict__ sv) {
    int t = blockIdx.x * 256 + threadIdx.x;
    int stride = gridDim.x * 256;
    for (int i = t; i < 160 * 128; i += stride) { int k = i >> 7, o = i & 127; g_wqT[i] = qw[o * 160 + k]; }
    for (int i = t; i < 160 * 32;  i += stride) { int k = i >> 5, a = i & 31;  g_wpT[i] = pw[a * 160 + k]; }
    for (int i = t; i < 128 * 32;  i += stride) { int k = i >> 5, m = i & 31;  g_wsvT[i] = sv[m * 128 + k]; }
}

// ============================================================
// KA (best measured variant, R6): 64 items/block, 512 threads.
// Warps 0-7 s_out (32x32 tiles); 8-15 logits then v_out acc.
// ============================================================
__global__ void __launch_bounds__(512) ka_gvp(
    const float* __restrict__ s, const float* __restrict__ v,
    const float* __restrict__ q_wh, const float* __restrict__ q_ws_b,
    const float* __restrict__ q_wv, const float* __restrict__ q_wsv_b,
    const float* __restrict__ wp_wh, const float* __restrict__ wp_ws_b)
{
    extern __shared__ float sm[];
    float* wq   = sm;            // [160][128]
    float* wp   = sm + 20480;    // [160][32]
    float* wsv  = sm + 25600;    // [128][32]
    float* whq  = sm + 29696;    // [32][34]
    float* whp  = sm + 30784;    // [32][34]
    float* wvvT = sm + 31872;    // [32][32]  (h-major)
    float* sbq  = sm + 32896;
    float* sbp  = sm + 33024;
    float* svb  = sm + 33056;
    float* xs   = sm + 33088;    // [160][66]
    float* vnp  = sm + 43648;    // [32][66]
    float* vhs  = sm + 45760;    // [64][97]
    float* gsb  = sm + 51968;    // [64][33]
    float* vbuf = sm + 54080;    // [16][104]  -> total 55744 floats

    int tid = threadIdx.x, warp = tid >> 5, lane = tid & 31;
    int base = blockIdx.x * 64;

    for (int i = tid; i < 20480; i += 512) wq[i]  = g_wqT[i];
    for (int i = tid; i < 5120;  i += 512) wp[i]  = g_wpT[i];
    for (int i = tid; i < 4096;  i += 512) wsv[i] = g_wsvT[i];
    for (int i = tid; i < 1024;  i += 512) {
        int r = i >> 5, cc = i & 31;
        whq[r * 34 + cc]  = q_wh[i];
        whp[r * 34 + cc]  = wp_wh[i];
        wvvT[i] = q_wv[(i & 31) * 32 + (i >> 5)];
    }
    if (tid < 128) sbq[tid] = q_ws_b[tid];
    if (tid < 32)  { sbp[tid] = wp_ws_b[tid]; svb[tid] = q_wsv_b[tid]; }
    __syncthreads();

    // ---- stage A
    {
        float* vb = vbuf + warp * 104;
        for (int ii = 0; ii < 4; ii++) {
            int i = warp * 4 + ii;
            size_t git = (size_t)(base + i);
            const float* sp = s + git * 128;
            const float* vp = v + git * 96;
            #pragma unroll
            for (int k = 0; k < 4; k++) xs[(lane + 32 * k) * 66 + i] = sp[lane + 32 * k];
            #pragma unroll
            for (int k = 0; k < 3; k++) {
                int pos = lane + 32 * k;
                float val = vp[pos];
                int m = pos / 3, d = pos - m * 3;
                vb[d * 34 + m] = val;
            }
            __syncwarp();
            ull aq0 = 0, aq1 = 0, aq2 = 0, ap0 = 0, ap1 = 0, ap2 = 0;
            #pragma unroll
            for (int m2 = 0; m2 < 32; m2 += 2) {
                ull wqp = *(const ull*)&whq[lane * 34 + m2];
                ull wpp = *(const ull*)&whp[lane * 34 + m2];
                ull v0 = *(const ull*)&vb[m2];
                ull v1 = *(const ull*)&vb[34 + m2];
                ull v2 = *(const ull*)&vb[68 + m2];
                FMA2(aq0, v0, wqp); FMA2(aq1, v1, wqp); FMA2(aq2, v2, wqp);
                FMA2(ap0, v0, wpp); FMA2(ap1, v1, wpp); FMA2(ap2, v2, wpp);
            }
            float2 f;
            f = unpk(aq0); float a0 = f.x + f.y;
            f = unpk(aq1); float a1 = f.x + f.y;
            f = unpk(aq2); float a2 = f.x + f.y;
            f = unpk(ap0); float b0 = f.x + f.y;
            f = unpk(ap1); float b1 = f.x + f.y;
            f = unpk(ap2); float b2 = f.x + f.y;
            vhs[i * 97 + lane] = a0; vhs[i * 97 + 32 + lane] = a1; vhs[i * 97 + 64 + lane] = a2;
            xs[(128 + lane) * 66 + i] = sqrtf(fmaxf(a0 * a0 + a1 * a1 + a2 * a2, 1e-8f));
            vnp[lane * 66 + i]        = sqrtf(fmaxf(b0 * b0 + b1 * b1 + b2 * b2, 1e-8f));
            __syncwarp();
        }
    }
    __syncthreads();

    ull acc[4][4] = {};   // s_out accs / later sig pairs
    ull vo[3][4]  = {};   // v_out accs

    if (warp < 8) {
        // ---- s_out: warp tile 32 items x 32 outs; thread 8i x 4o
        int itile = (warp & 1) * 32, otile = (warp >> 1) * 32;
        int r = lane >> 3, cc = lane & 7;
        const float* xb = xs + itile + r * 8;
        const float* wb = wq + otile + cc * 4;
        #pragma unroll 2
        for (int k = 0; k < 160; k++) {
            ull x0 = *(const ull*)(xb + k * 66);
            ull x1 = *(const ull*)(xb + k * 66 + 2);
            ull x2 = *(const ull*)(xb + k * 66 + 4);
            ull x3 = *(const ull*)(xb + k * 66 + 6);
            float4 wf = *(const float4*)(wb + k * 128);
            ull w0 = packx2(wf.x), w1 = packx2(wf.y), w2 = packx2(wf.z), w3 = packx2(wf.w);
            FMA2(acc[0][0], x0, w0); FMA2(acc[0][1], x0, w1); FMA2(acc[0][2], x0, w2); FMA2(acc[0][3], x0, w3);
            FMA2(acc[1][0], x1, w0); FMA2(acc[1][1], x1, w1); FMA2(acc[1][2], x1, w2); FMA2(acc[1][3], x1, w3);
            FMA2(acc[2][0], x2, w0); FMA2(acc[2][1], x2, w1); FMA2(acc[2][2], x2, w2); FMA2(acc[2][3], x2, w3);
            FMA2(acc[3][0], x3, w0); FMA2(acc[3][1], x3, w1); FMA2(acc[3][2], x3, w2); FMA2(acc[3][3], x3, w3);
        }
        float bb[4];
        #pragma unroll
        for (int u = 0; u < 4; u++) bb[u] = sbq[otile + cc * 4 + u];
        int head = otile >> 5;
        #pragma unroll
        for (int p = 0; p < 4; p++) {
            int i0 = itile + r * 8 + 2 * p;
            float s0[4], s1[4];
            #pragma unroll
            for (int u = 0; u < 4; u++) {
                float2 fr = unpk(acc[p][u]);
                float soa = fr.x + bb[u], sob = fr.y + bb[u];
                float ga = sigf(soa), gb = sigf(sob);
                s0[u] = soa * ga; s1[u] = sob * gb;
                acc[p][u] = pack2(ga, gb);
            }
            *(float4*)&g_q[(size_t)(base + i0) * 224 + head * 56 + cc * 4] =
                make_float4(s0[0], s0[1], s0[2], s0[3]);
            *(float4*)&g_q[(size_t)(base + i0 + 1) * 224 + head * 56 + cc * 4] =
                make_float4(s1[0], s1[1], s1[2], s1[3]);
        }
    } else {
        int t2 = tid - 256;
        int i = t2 & 63, jg = t2 >> 6;
        // ---- logits: thread = 1 item x 8 outs
        {
            ull la[4] = {};
            const float* wrow = wp + jg * 8;
            #pragma unroll 2
            for (int k = 0; k < 128; k++) {
                ull xp = packx2(xs[k * 66 + i]);
                double2 wa = *(const double2*)(wrow + k * 32);
                double2 wb2 = *(const double2*)(wrow + k * 32 + 4);
                FMA2(la[0], xp, __double_as_longlong(wa.x));
                FMA2(la[1], xp, __double_as_longlong(wa.y));
                FMA2(la[2], xp, __double_as_longlong(wb2.x));
                FMA2(la[3], xp, __double_as_longlong(wb2.y));
            }
            #pragma unroll 2
            for (int k = 0; k < 32; k++) {
                ull xp = packx2(vnp[k * 66 + i]);
                double2 wa = *(const double2*)(wrow + (128 + k) * 32);
                double2 wb2 = *(const double2*)(wrow + (128 + k) * 32 + 4);
                FMA2(la[0], xp, __double_as_longlong(wa.x));
                FMA2(la[1], xp, __double_as_longlong(wa.y));
                FMA2(la[2], xp, __double_as_longlong(wb2.x));
                FMA2(la[3], xp, __double_as_longlong(wb2.y));
            }
            float2 f0 = unpk(la[0]), f1 = unpk(la[1]), f2 = unpk(la[2]), f3 = unpk(la[3]);
            const float* bp = sbp + jg * 8;
            size_t gl = (size_t)(base + i) * 32 + jg * 8;
            *(float4*)&g_logits[gl]     = make_float4(f0.x + bp[0], f0.y + bp[1], f1.x + bp[2], f1.y + bp[3]);
            *(float4*)&g_logits[gl + 4] = make_float4(f2.x + bp[4], f2.y + bp[5], f3.x + bp[6], f3.y + bp[7]);
        }
        // ---- v_out accumulate (gate deferred)
        {
            const float* wvb = wvvT + jg * 8;
            const float* vr = vhs + i * 97;
            #pragma unroll 2
            for (int h = 0; h < 32; h++) {
                ull v0 = packx2(vr[h]);
                ull v1 = packx2(vr[32 + h]);
                ull v2 = packx2(vr[64 + h]);
                double2 wa = *(const double2*)(wvb + h * 32);
                double2 wb2 = *(const double2*)(wvb + h * 32 + 4);
                ull w0 = __double_as_longlong(wa.x), w1 = __double_as_longlong(wa.y);
                ull w2 = __double_as_longlong(wb2.x), w3 = __double_as_longlong(wb2.y);
                FMA2(vo[0][0], v0, w0); FMA2(vo[0][1], v0, w1); FMA2(vo[0][2], v0, w2); FMA2(vo[0][3], v0, w3);
                FMA2(vo[1][0], v1, w0); FMA2(vo[1][1], v1, w1); FMA2(vo[1][2], v1, w2); FMA2(vo[1][3], v1, w3);
                FMA2(vo[2][0], v2, w0); FMA2(vo[2][1], v2, w1); FMA2(vo[2][2], v2, w2); FMA2(vo[2][3], v2, w3);
            }
        }
    }
    __syncthreads();

    if (warp < 8) {
        int itile = (warp & 1) * 32, otile = (warp >> 1) * 32;
        int r = lane >> 3, cc = lane & 7;
        #pragma unroll
        for (int p = 0; p < 4; p++) {
            int i0 = itile + r * 8 + 2 * p;
            #pragma unroll
            for (int u = 0; u < 4; u++) {
                float2 fr = unpk(acc[p][u]);
                int o = otile + cc * 4 + u;
                xs[o * 66 + i0]     = fr.x;
                xs[o * 66 + i0 + 1] = fr.y;
            }
        }
    }
    __syncthreads();

    // ---- gate: thread = 1 item x 4 m
    {
        int j = tid & 7, ig = tid >> 3;
        ull ga[2] = {};
        const float* wrow = wsv + j * 4;
        #pragma unroll 4
        for (int o = 0; o < 128; o++) {
            ull xp = packx2(xs[o * 66 + ig]);
            double2 wd = *(const double2*)(wrow + o * 32);
            FMA2(ga[0], xp, __double_as_longlong(wd.x));
            FMA2(ga[1], xp, __double_as_longlong(wd.y));
        }
        float2 f0 = unpk(ga[0]), f1 = unpk(ga[1]);
        gsb[ig * 33 + j * 4 + 0] = sigf(f0.x + svb[j * 4 + 0]);
        gsb[ig * 33 + j * 4 + 1] = sigf(f0.y + svb[j * 4 + 1]);
        gsb[ig * 33 + j * 4 + 2] = sigf(f1.x + svb[j * 4 + 2]);
        gsb[ig * 33 + j * 4 + 3] = sigf(f1.y + svb[j * 4 + 3]);
    }
    __syncthreads();

    if (warp >= 8) {
        int t2 = tid - 256;
        int i = t2 & 63, mg = t2 >> 6;
        #pragma unroll
        for (int mp = 0; mp < 4; mp++) {
            int m0 = mg * 8 + 2 * mp;
            float g0 = gsb[i * 33 + m0], g1 = gsb[i * 33 + m0 + 1];
            #pragma unroll
            for (int d = 0; d < 3; d++) {
                float2 fr = unpk(vo[d][mp]);
                vhs[i * 97 + m0 * 3 + d]       = fr.x * g0;
                vhs[i * 97 + (m0 + 1) * 3 + d] = fr.y * g1;
            }
        }
        asm volatile("bar.sync 1, 256;" ::: "memory");
        int wi = warp - 8;
        for (int ii = 0; ii < 8; ii++) {
            int item = wi * 8 + ii;
            size_t gb2 = (size_t)(base + item) * 224;
            #pragma unroll
            for (int q = 0; q < 3; q++) {
                int l = lane + 32 * q;
                int m = l / 3, d = l - m * 3;
                int gpos = (m >> 3) * 56 + 32 + (m & 7) * 3 + d;
                g_q[gb2 + gpos] = vhs[item * 97 + l];
            }
        }
    }
}

// ---- K2a: per-(c,seg) partial online softmax stats ----
__global__ void __launch_bounds__(256) k2a_stats() {
    __shared__ float redm[8 * 33], reds[8 * 33];
    int seg = blockIdx.x, c = blockIdx.y;
    int t = threadIdx.x, a = t & 31, part = t >> 5;
    float m = -3.4e38f, sum = 0.f;
    int nb = seg * 512 + part * 64;
    for (int i = 0; i < 64; i++) {
        float val = g_logits[((size_t)(nb + i) * C_DIM + c) * 32 + a];
        float nm = fmaxf(m, val);
        sum = sum * __expf(m - nm) + __expf(val - nm);
        m = nm;
    }
    redm[part * 33 + a] = m; reds[part * 33 + a] = sum;
    __syncthreads();
    if (t < 32) {
        float mm = redm[t], ss = reds[t];
        #pragma unroll
        for (int p = 1; p < 8; p++) {
            float m2 = redm[p * 33 + t], s2 = reds[p * 33 + t];
            float nm = fmaxf(mm, m2);
            ss = ss * __expf(mm - nm) + s2 * __expf(m2 - nm);
            mm = nm;
        }
        g_pm[(c * 16 + seg) * 32 + t] = mm;
        g_ps[(c * 16 + seg) * 32 + t] = ss;
    }
}

// ---- K3: compress partials, DOUBLE-BUFFERED (profiled launch) ----
__global__ void __launch_bounds__(224) k3_compress(const float* __restrict__ s,
                                                   const float* __restrict__ v) {
    __shared__ float xt[2][32 * 226];
    __shared__ float wt[2][32 * 33];
    __shared__ float mloc[32], iloc[32];
    int t = threadIdx.x;
    int chunk = blockIdx.x, c = blockIdx.y;

    // prologue: xt[0] loads + softmax-stat merge, overlapped
    #pragma unroll 4
    for (int n = 0; n < 32; n++) {
        int item = (chunk * 128 + n) * C_DIM + c;
        xt[0][n * 226 + t] = (t < 128) ? s[(size_t)item * 128 + t]
                                       : v[(size_t)item * 96 + (t - 128)];
    }
    if (t < 32) {
        float m = -3.4e38f;
        #pragma unroll
        for (int sg2 = 0; sg2 < 16; sg2++) m = fmaxf(m, g_pm[(c * 16 + sg2) * 32 + t]);
        float sum = 0.f;
        #pragma unroll
        for (int sg2 = 0; sg2 < 16; sg2++)
            sum += g_ps[(c * 16 + sg2) * 32 + t] * __expf(g_pm[(c * 16 + sg2) * 32 + t] - m);
        mloc[t] = m; iloc[t] = 1.0f / sum;
    }
    __syncthreads();   // mloc + xt[0] ready
    for (int idx = t; idx < 1024; idx += 224) {
        int n = idx >> 5, a = idx & 31;
        int item = (chunk * 128 + n) * C_DIM + c;
        wt[0][n * 33 + a] = __expf(g_logits[(size_t)item * 32 + a] - mloc[a]) * iloc[a];
    }
    __syncthreads();   // wt[0] ready

    int a0 = (t & 7) * 4, j0 = (t >> 3) * 8;
    ull acc[4][4] = {};
    for (int sub = 0; sub < 4; sub++) {
        int cur = sub & 1, nxt = cur ^ 1;
        if (sub < 3) {
            // issue next-sub loads; latency hidden under compute below
            #pragma unroll 4
            for (int n = 0; n < 32; n++) {
                int item = (chunk * 128 + (sub + 1) * 32 + n) * C_DIM + c;
                xt[nxt][n * 226 + t] = (t < 128) ? s[(size_t)item * 128 + t]
                                                 : v[(size_t)item * 96 + (t - 128)];
            }
            for (int idx = t; idx < 1024; idx += 224) {
                int n = idx >> 5, a = idx & 31;
                int item = (chunk * 128 + (sub + 1) * 32 + n) * C_DIM + c;
                wt[nxt][n * 33 + a] = __expf(g_logits[(size_t)item * 32 + a] - mloc[a]) * iloc[a];
            }
        }
        #pragma unroll 4
        for (int n = 0; n < 32; n++) {
            ull wpk[4];
            #pragma unroll
            for (int u = 0; u < 4; u++) wpk[u] = packx2(wt[cur][n * 33 + a0 + u]);
            const ull* x2 = (const ull*)(xt[cur] + n * 226 + j0);
            #pragma unroll
            for (int vv = 0; vv < 4; vv++) {
                ull xp = x2[vv];
                FMA2(acc[0][vv], wpk[0], xp);
                FMA2(acc[1][vv], wpk[1], xp);
                FMA2(acc[2][vv], wpk[2], xp);
                FMA2(acc[3][vv], wpk[3], xp);
            }
        }
        __syncthreads();
    }
    #pragma unroll
    for (int u = 0; u < 4; u++) {
        size_t basep = ((size_t)(chunk * C_DIM + c) * 32 + a0 + u) * 224 + j0;
        #pragma unroll
        for (int vv = 0; vv < 4; vv++) {
            float2 fr = unpk(acc[u][vv]);
            *(float2*)&g_part[basep + 2 * vv] = fr;
        }
    }
}

// ---- K4 ----
__global__ void k4_reduce() {
    int bx = blockIdx.x; int c = bx >> 5, a = bx & 31; int t = threadIdx.x;
    float sum = 0.f;
    for (int ch = 0; ch < NCHUNK; ++ch)
        sum += g_part[((size_t)(ch * C_DIM + c) * 32 + a) * 224 + t];
    g_gbuf[(a * C_DIM + c) * 224 + t] = sum;
}

// ---- K5 ----
__global__ void k5_globals(
    const float* __restrict__ k_wh, const float* __restrict__ k_ws_w, const float* __restrict__ k_ws_b,
    const float* __restrict__ k_wv, const float* __restrict__ k_wsv_w, const float* __restrict__ k_wsv_b,
    const float* __restrict__ p_wh, const float* __restrict__ p_ws_w, const float* __restrict__ p_ws_b,
    const float* __restrict__ p_wv, const float* __restrict__ p_wsv_w, const float* __restrict__ p_wsv_b) {
    __shared__ float wx[8][608];
    int tid = threadIdx.x, warp = tid >> 5, lane = tid & 31;
    int w = blockIdx.x * 8 + warp;
    int which = w >> 9, item = w & 511;
    const float* wh   = which ? p_wh    : k_wh;
    const float* wsw  = which ? p_ws_w  : k_ws_w;
    const float* wsb  = which ? p_ws_b  : k_ws_b;
    const float* wv   = which ? p_wv    : k_wv;
    const float* wsvw = which ? p_wsv_w : k_wsv_w;
    const float* wsvb = which ? p_wsv_b : k_wsv_b;
    float* x = wx[warp]; float* vhsl = x + 224; float* vns = x + 320; float* sig = x + 480;
    const float* gp = &g_gbuf[item * 224];
    #pragma unroll
    for (int k = 0; k < 7; k++) x[lane + 32 * k] = gp[lane + 32 * k];
    __syncwarp();
    float a0 = 0.f, a1 = 0.f, a2 = 0.f;
    #pragma unroll
    for (int i = 0; i < 32; i++) {
        float ww = __ldg(&wh[lane * 32 + i]);
        a0 = fmaf(x[128 + i * 3 + 0], ww, a0);
        a1 = fmaf(x[128 + i * 3 + 1], ww, a1);
        a2 = fmaf(x[128 + i * 3 + 2], ww, a2);
    }
    vhsl[lane] = a0; vhsl[32 + lane] = a1; vhsl[64 + lane] = a2;
    vns[lane] = sqrtf(fmaxf(a0 * a0 + a1 * a1 + a2 * a2, 1e-8f));
    __syncwarp();
    float so[4];
    #pragma unroll
    for (int k = 0; k < 4; k++) {
        int o = lane + 32 * k;
        float acc = __ldg(&wsb[o]);
        const float* wr = &wsw[o * 160];
        #pragma unroll
        for (int j = 0; j < 128; j++) acc = fmaf(x[j], __ldg(&wr[j]), acc);
        #pragma unroll
        for (int j = 0; j < 32; j++) acc = fmaf(vns[j], __ldg(&wr[128 + j]), acc);
        so[k] = acc;
        sig[o] = sigf(acc);
    }
    __syncwarp();
    float g = __ldg(&wsvb[lane]);
    #pragma unroll
    for (int j = 0; j < 128; j++) g = fmaf(sig[j], __ldg(&wsvw[lane * 128 + j]), g);
    float gs = sigf(g);
    float* outp = which ? g_ve : g_ke;
    int a = item >> 4, cc = item & 15;
    size_t ob = ((size_t)cc * 32 + a) * 224;
    int h = lane >> 3;
    int vpos = h * 56 + 32 + (lane & 7) * 3;
    #pragma unroll
    for (int d = 0; d < 3; d++) {
        float vo = 0.f;
        #pragma unroll
        for (int hh = 0; hh < 32; hh++) vo = fmaf(vhsl[d * 32 + hh], __ldg(&wv[lane * 32 + hh]), vo);
        outp[ob + vpos + d] = vo * gs;
    }
    #pragma unroll
    for (int k = 0; k < 4; k++) { int o = lane + 32 * k; outp[ob + k * 56 + lane] = so[k] * sig[o]; }
}

// ---- KB: attention, 32 items x 1 channel, 256 threads ----
__global__ void __launch_bounds__(256) kb_attn(float* __restrict__ out) {
    extern __shared__ float sm[];
    float* qe  = sm;            // [224][33]
    float* keT = sm + 7392;     // [224][34]
    float* ve  = sm + 15008;    // [32][226]
    float* al  = sm + 22240;    // [32][133]
    int tid = threadIdx.x;
    int c = blockIdx.y;
    int nb = blockIdx.x * 32;

    for (int idx = tid; idx < 32 * 224; idx += 256) {
        int i = idx / 224, pos = idx - i * 224;
        size_t git = (size_t)(nb + i) * 16 + c;
        qe[pos * 33 + i] = g_q[git * 224 + pos];
    }
    for (int idx = tid; idx < 32 * 224; idx += 256) {
        int r = idx / 224, pos = idx - r * 224;
        size_t gb = ((size_t)c * 32 + r) * 224 + pos;
        keT[pos * 34 + r] = g_ke[gb];
        ve[r * 226 + pos] = g_ve[gb];
    }
    __syncthreads();

    int h = tid >> 6, rem = tid & 63;

    {
        int ig = rem >> 3, rg = rem & 7;
        ull acc[4][2] = {};
        #pragma unroll 2
        for (int k = 0; k < 56; k++) {
            int row = h * 56 + k;
            ull qp[4];
            #pragma unroll
            for (int e = 0; e < 4; e++) qp[e] = packx2(qe[row * 33 + ig * 4 + e]);
            const ull* k2 = (const ull*)(keT + row * 34 + rg * 4);
            #pragma unroll
            for (int u = 0; u < 2; u++) {
                ull kp = k2[u];
                FMA2(acc[0][u], qp[0], kp);
                FMA2(acc[1][u], qp[1], kp);
                FMA2(acc[2][u], qp[2], kp);
                FMA2(acc[3][u], qp[3], kp);
            }
        }
        #pragma unroll
        for (int e = 0; e < 4; e++)
            #pragma unroll
            for (int u = 0; u < 2; u++) {
                float2 fr = unpk(acc[e][u]);
                al[(ig * 4 + e) * 133 + h * 33 + rg * 4 + 2 * u]     = fr.x * ESCALE;
                al[(ig * 4 + e) * 133 + h * 33 + rg * 4 + 2 * u + 1] = fr.y * ESCALE;
            }
    }
    __syncthreads();

    if (tid < 128) {
        int i = tid >> 2, h2 = tid & 3;
        float* row = &al[i * 133 + h2 * 33];
        float ev[32], mx = -3.4e38f;
        #pragma unroll
        for (int k = 0; k < 32; k++) { ev[k] = row[k]; mx = fmaxf(mx, ev[k]); }
        float sum = 0.f;
        #pragma unroll
        for (int k = 0; k < 32; k++) { ev[k] = __expf(ev[k] - mx); sum += ev[k]; }
        float inv = 1.0f / sum;
        #pragma unroll
        for (int k = 0; k < 32; k++) row[k] = ev[k] * inv;
    }
    __syncthreads();

    {
        int ig = rem >> 2, j = rem & 3;
        ull accs[2][4] = {};
        ull accv[2][3] = {};
        #pragma unroll 2
        for (int r = 0; r < 32; r++) {
            ull ap[2];
            #pragma unroll
            for (int e = 0; e < 2; e++) ap[e] = packx2(al[(ig * 2 + e) * 133 + h * 33 + r]);
            const ull* vs2 = (const ull*)(ve + r * 226 + h * 56 + j * 8);
            const ull* vv2 = (const ull*)(ve + r * 226 + h * 56 + 32 + j * 6);
            #pragma unroll
            for (int u = 0; u < 4; u++) {
                ull vp = vs2[u];
                FMA2(accs[0][u], ap[0], vp);
                FMA2(accs[1][u], ap[1], vp);
            }
            #pragma unroll
            for (int u = 0; u < 3; u++) {
                ull vp = vv2[u];
                FMA2(accv[0][u], ap[0], vp);
                FMA2(accv[1][u], ap[1], vp);
            }
        }
        #pragma unroll
        for (int e = 0; e < 2; e++) {
            size_t git = (size_t)(nb + ig * 2 + e) * 16 + c;
            float* ds = &out[git * 128 + h * 32 + j * 8];
            #pragma unroll
            for (int u = 0; u < 4; u++) *(float2*)&ds[2 * u] = unpk(accs[e][u]);
            float* dv = &out[(size_t)NC_ITEMS * 128 + git * 96 + h * 24 + j * 6];
            #pragma unroll
            for (int u = 0; u < 3; u++) *(float2*)&dv[2 * u] = unpk(accv[e][u]);
        }
    }
}

// ============================================================
extern "C" void kernel_launch(void* const* d_in, const int* in_sizes, int n_in,
                              void* d_out, int out_size) {
    (void)in_sizes; (void)n_in; (void)out_size;
    const float* s       = (const float*)d_in[0];
    const float* v       = (const float*)d_in[1];
    const float* wp_wh   = (const float*)d_in[2];
    const float* wp_ws_w = (const float*)d_in[3];
    const float* wp_ws_b = (const float*)d_in[4];
    const float* q_wh    = (const float*)d_in[5];
    const float* q_ws_w  = (const float*)d_in[6];
    const float* q_ws_b  = (const float*)d_in[7];
    const float* q_wv    = (const float*)d_in[8];
    const float* q_wsv_w = (const float*)d_in[9];
    const float* q_wsv_b = (const float*)d_in[10];
    const float* k_wh    = (const float*)d_in[11];
    const float* k_ws_w  = (const float*)d_in[12];
    const float* k_ws_b  = (const float*)d_in[13];
    const float* k_wv    = (const float*)d_in[14];
    const float* k_wsv_w = (const float*)d_in[15];
    const float* k_wsv_b = (const float*)d_in[16];
    const float* vp_wh   = (const float*)d_in[17];
    const float* vp_ws_w = (const float*)d_in[18];
    const float* vp_ws_b = (const float*)d_in[19];
    const float* vp_wv   = (const float*)d_in[20];
    const float* vp_wsv_w= (const float*)d_in[21];
    const float* vp_wsv_b= (const float*)d_in[22];
    float* out = (float*)d_out;

    cudaFuncSetAttribute((const void*)ka_gvp,  cudaFuncAttributeMaxDynamicSharedMemorySize, 55744 * 4);
    cudaFuncSetAttribute((const void*)kb_attn, cudaFuncAttributeMaxDynamicSharedMemorySize, 26496 * 4);

    k0_transpose<<<32, 256>>>(q_ws_w, wp_ws_w, q_wsv_w);
    ka_gvp<<<2048, 512, 55744 * 4>>>(s, v, q_wh, q_ws_b, q_wv, q_wsv_b, wp_wh, wp_ws_b);
    k2a_stats<<<dim3(16, 16), 256>>>();
    k3_compress<<<dim3(NCHUNK, C_DIM), 224>>>(s, v);   // 4th launch -> profiled
    k4_reduce<<<512, 224>>>();
    k5_globals<<<128, 256>>>(k_wh, k_ws_w, k_ws_b, k_wv, k_wsv_w, k_wsv_b,
                             vp_wh, vp_ws_w, vp_ws_b, vp_wv, vp_wsv_w, vp_wsv_b);
    kb_attn<<<dim3(256, C_DIM), 256, 26496 * 4>>>(out);
}

// round 12
// speedup vs baseline: 1.0851x; 1.0851x over previous
#include <cuda_runtime.h>

#define N_NODES 8192
#define C_DIM   16
#define NC_ITEMS (N_NODES * C_DIM)
#define R_ANCH  32
#define XD      224
#define NCHUNK  64
#define ESCALE  0.15811388300841898f

typedef unsigned long long ull;
typedef unsigned int uint;

__device__ float g_logits[NC_ITEMS * R_ANCH];
__device__ float g_pm[C_DIM * 16 * R_ANCH];
__device__ float g_ps[C_DIM * 16 * R_ANCH];
__device__ float g_part[NCHUNK * C_DIM * R_ANCH * XD];
__device__ float g_gbuf[R_ANCH * C_DIM * XD];
__device__ float g_ke[C_DIM * R_ANCH * XD];
__device__ float g_ve[C_DIM * R_ANCH * XD];
__device__ float g_q[(size_t)NC_ITEMS * XD];
__device__ float g_wpT[160 * 32];
__device__ float g_wsvT[128 * 32];

__device__ __forceinline__ float sigf(float x) { return 1.0f / (1.0f + __expf(-x)); }
#define FMA2(d, a, b) asm("fma.rn.f32x2 %0, %1, %2, %0;" : "+l"(d) : "l"(a), "l"(b))
__device__ __forceinline__ ull packx2(float x) {
    ull o; unsigned r = __float_as_uint(x);
    asm("mov.b64 %0, {%1, %1};" : "=l"(o) : "r"(r));
    return o;
}
__device__ __forceinline__ float2 unpk(ull u) {
    float2 f;
    asm("mov.b64 {%0, %1}, %2;" : "=f"(f.x), "=f"(f.y) : "l"(u));
    return f;
}
__device__ __forceinline__ uint tf32c(float f) {
    uint u;
    asm("cvt.rna.tf32.f32 %0, %1;" : "=r"(u) : "f"(f));
    return u;
}
#define MMA_TF32(d, a0, a1, a2, a3, b0, b1) \
    asm volatile("mma.sync.aligned.m16n8k8.row.col.f32.tf32.tf32.f32 " \
        "{%0,%1,%2,%3}, {%4,%5,%6,%7}, {%8,%9}, {%0,%1,%2,%3};" \
        : "+f"(d[0]), "+f"(d[1]), "+f"(d[2]), "+f"(d[3]) \
        : "r"(a0), "r"(a1), "r"(a2), "r"(a3), "r"(b0), "r"(b1))

// ---- splash + transposes (ka stays 4th launch = profiled) ----
__global__ void kz() { if (threadIdx.x == 0) g_pm[0] = 0.f; }
__global__ void k0b(const float* __restrict__ pw) {
    int i = blockIdx.x * 256 + threadIdx.x;
    if (i < 160 * 32) { int k = i >> 5, a = i & 31; g_wpT[i] = pw[a * 160 + k]; }
}
__global__ void k0c(const float* __restrict__ sv) {
    int i = blockIdx.x * 256 + threadIdx.x;
    if (i < 128 * 32) { int k = i >> 5, m = i & 31; g_wsvT[i] = sv[m * 128 + k]; }
}

// ---- ka smem offsets (floats) ----
#define OF_WQOM 0        // [128][164] tf32 bits, [o][k]
#define OF_WP   20992    // [160][32] k-major
#define OF_WSV  26112    // [128][32] k-major
#define OF_WHQ  30208    // [32][34]
#define OF_WHP  31296
#define OF_WVVT 32384    // [32][32] h-major
#define OF_SBQ  33408
#define OF_SBP  33536
#define OF_SVB  33568
#define OF_XS   33600    // [160][68]: rows 0..127 x_s/sig, 128..159 vn_q
#define OF_VNP  44480    // [32][66]
#define OF_VHS  46592    // [64][97]
#define OF_GSB  52800    // [64][33]
#define OF_VBUF 54912    // [16][104]
#define KA_SMEMF 56576

// ============================================================
// KA: 64 items/block, 512 threads.
// Phase B: warps 0-7 s_out via tf32 mma; warps 8-15 logits + v_out.
// ============================================================
__global__ void __launch_bounds__(512) ka_gvp(
    const float* __restrict__ s, const float* __restrict__ v,
    const float* __restrict__ q_wh, const float* __restrict__ q_ws_w,
    const float* __restrict__ q_ws_b, const float* __restrict__ q_wv,
    const float* __restrict__ q_wsv_b,
    const float* __restrict__ wp_wh, const float* __restrict__ wp_ws_b)
{
    extern __shared__ float sm[];
    float* wqom = sm + OF_WQOM;
    float* wp   = sm + OF_WP;
    float* wsv  = sm + OF_WSV;
    float* whq  = sm + OF_WHQ;
    float* whp  = sm + OF_WHP;
    float* wvvT = sm + OF_WVVT;
    float* sbq  = sm + OF_SBQ;
    float* sbp  = sm + OF_SBP;
    float* svb  = sm + OF_SVB;
    float* xs   = sm + OF_XS;
    float* vnp  = sm + OF_VNP;
    float* vhs  = sm + OF_VHS;
    float* gsb  = sm + OF_GSB;
    float* vbuf = sm + OF_VBUF;

    int tid = threadIdx.x, warp = tid >> 5, lane = tid & 31;
    int base = blockIdx.x * 64;

    for (int i = tid; i < 128 * 160; i += 512) {
        int r = i / 160, c = i - r * 160;
        wqom[r * 164 + c] = __uint_as_float(tf32c(q_ws_w[i]));   // [o][k] tf32
    }
    for (int i = tid; i < 5120; i += 512) wp[i]  = g_wpT[i];
    for (int i = tid; i < 4096; i += 512) wsv[i] = g_wsvT[i];
    for (int i = tid; i < 1024; i += 512) {
        int r = i >> 5, cc = i & 31;
        whq[r * 34 + cc] = q_wh[i];
        whp[r * 34 + cc] = wp_wh[i];
        wvvT[i] = q_wv[(i & 31) * 32 + (i >> 5)];
    }
    if (tid < 128) sbq[tid] = q_ws_b[tid];
    if (tid < 32)  { sbp[tid] = wp_ws_b[tid]; svb[tid] = q_wsv_b[tid]; }
    __syncthreads();

    // ---- stage A: 16 warps x 4 items
    {
        float* vb = vbuf + warp * 104;
        for (int ii = 0; ii < 4; ii++) {
            int i = warp * 4 + ii;
            size_t git = (size_t)(base + i);
            const float* sp = s + git * 128;
            const float* vpp = v + git * 96;
            #pragma unroll
            for (int k = 0; k < 4; k++) xs[(lane + 32 * k) * 68 + i] = sp[lane + 32 * k];
            #pragma unroll
            for (int k = 0; k < 3; k++) {
                int pos = lane + 32 * k;
                float val = vpp[pos];
                int m = pos / 3, d = pos - m * 3;
                vb[d * 34 + m] = val;
            }
            __syncwarp();
            ull aq0 = 0, aq1 = 0, aq2 = 0, ap0 = 0, ap1 = 0, ap2 = 0;
            #pragma unroll
            for (int m2 = 0; m2 < 32; m2 += 2) {
                ull wqp = *(const ull*)&whq[lane * 34 + m2];
                ull wpp = *(const ull*)&whp[lane * 34 + m2];
                ull v0 = *(const ull*)&vb[m2];
                ull v1 = *(const ull*)&vb[34 + m2];
                ull v2 = *(const ull*)&vb[68 + m2];
                FMA2(aq0, v0, wqp); FMA2(aq1, v1, wqp); FMA2(aq2, v2, wqp);
                FMA2(ap0, v0, wpp); FMA2(ap1, v1, wpp); FMA2(ap2, v2, wpp);
            }
            float2 f;
            f = unpk(aq0); float a0 = f.x + f.y;
            f = unpk(aq1); float a1 = f.x + f.y;
            f = unpk(aq2); float a2 = f.x + f.y;
            f = unpk(ap0); float b0 = f.x + f.y;
            f = unpk(ap1); float b1 = f.x + f.y;
            f = unpk(ap2); float b2 = f.x + f.y;
            vhs[i * 97 + lane] = a0; vhs[i * 97 + 32 + lane] = a1; vhs[i * 97 + 64 + lane] = a2;
            xs[(128 + lane) * 68 + i] = sqrtf(fmaxf(a0 * a0 + a1 * a1 + a2 * a2, 1e-8f));
            vnp[lane * 66 + i]        = sqrtf(fmaxf(b0 * b0 + b1 * b1 + b2 * b2, 1e-8f));
            __syncwarp();
        }
    }
    __syncthreads();

    float sg[8][4];   // sigmoids held across barrier (warps 0-7)
    ull vo[3][4] = {}; // v_out accs (warps 8-15)

    if (warp < 8) {
        // ---- s_out via tf32 mma: warp = 16 items x 64 outs
        int itile = (warp & 3) * 16, n0base = (warp >> 2) * 64;
        int tg = lane >> 2, tq = lane & 3;       // t/4, t%4
        float d[8][4] = {};
        #pragma unroll
        for (int kk = 0; kk < 20; kk++) {
            int kb = kk * 8;
            uint a0 = tf32c(xs[(kb + tq) * 68 + itile + tg]);
            uint a1 = tf32c(xs[(kb + tq) * 68 + itile + tg + 8]);
            uint a2 = tf32c(xs[(kb + tq + 4) * 68 + itile + tg]);
            uint a3 = tf32c(xs[(kb + tq + 4) * 68 + itile + tg + 8]);
            #pragma unroll
            for (int nt = 0; nt < 8; nt++) {
                const float* wb = wqom + (n0base + nt * 8 + tg) * 164 + kb + tq;
                uint b0 = __float_as_uint(wb[0]);
                uint b1 = __float_as_uint(wb[4]);
                MMA_TF32(d[nt], a0, a1, a2, a3, b0, b1);
            }
        }
        // epilogue: bias + silu -> g_q; sigmoids kept in regs
        #pragma unroll
        for (int nt = 0; nt < 8; nt++) {
            int o = n0base + nt * 8 + 2 * tq;
            float bb0 = sbq[o], bb1 = sbq[o + 1];
            int gp0 = (o >> 5) * 56 + (o & 31);
            int i_lo = itile + tg, i_hi = i_lo + 8;
            float s00 = d[nt][0] + bb0, s01 = d[nt][1] + bb1;
            float s10 = d[nt][2] + bb0, s11 = d[nt][3] + bb1;
            float g00 = sigf(s00), g01 = sigf(s01), g10 = sigf(s10), g11 = sigf(s11);
            sg[nt][0] = g00; sg[nt][1] = g01; sg[nt][2] = g10; sg[nt][3] = g11;
            *(float2*)&g_q[(size_t)(base + i_lo) * 224 + gp0] = make_float2(s00 * g00, s01 * g01);
            *(float2*)&g_q[(size_t)(base + i_hi) * 224 + gp0] = make_float2(s10 * g10, s11 * g11);
        }
    } else {
        int t2 = tid - 256;
        int i = t2 & 63, jg = t2 >> 6;
        // ---- logits (fp32): thread = 1 item x 8 outs
        {
            ull la[4] = {};
            const float* wrow = wp + jg * 8;
            #pragma unroll 2
            for (int k = 0; k < 128; k++) {
                ull xp = packx2(xs[k * 68 + i]);
                double2 wa = *(const double2*)(wrow + k * 32);
                double2 wb2 = *(const double2*)(wrow + k * 32 + 4);
                FMA2(la[0], xp, __double_as_longlong(wa.x));
                FMA2(la[1], xp, __double_as_longlong(wa.y));
                FMA2(la[2], xp, __double_as_longlong(wb2.x));
                FMA2(la[3], xp, __double_as_longlong(wb2.y));
            }
            #pragma unroll 2
            for (int k = 0; k < 32; k++) {
                ull xp = packx2(vnp[k * 66 + i]);
                double2 wa = *(const double2*)(wrow + (128 + k) * 32);
                double2 wb2 = *(const double2*)(wrow + (128 + k) * 32 + 4);
                FMA2(la[0], xp, __double_as_longlong(wa.x));
                FMA2(la[1], xp, __double_as_longlong(wa.y));
                FMA2(la[2], xp, __double_as_longlong(wb2.x));
                FMA2(la[3], xp, __double_as_longlong(wb2.y));
            }
            float2 f0 = unpk(la[0]), f1 = unpk(la[1]), f2 = unpk(la[2]), f3 = unpk(la[3]);
            const float* bp = sbp + jg * 8;
            size_t gl = (size_t)(base + i) * 32 + jg * 8;
            *(float4*)&g_logits[gl]     = make_float4(f0.x + bp[0], f0.y + bp[1], f1.x + bp[2], f1.y + bp[3]);
            *(float4*)&g_logits[gl + 4] = make_float4(f2.x + bp[4], f2.y + bp[5], f3.x + bp[6], f3.y + bp[7]);
        }
        // ---- v_out accumulate (gate deferred)
        {
            const float* wvb = wvvT + jg * 8;
            const float* vr = vhs + i * 97;
            #pragma unroll 2
            for (int h = 0; h < 32; h++) {
                ull v0 = packx2(vr[h]);
                ull v1 = packx2(vr[32 + h]);
                ull v2 = packx2(vr[64 + h]);
                double2 wa = *(const double2*)(wvb + h * 32);
                double2 wb2 = *(const double2*)(wvb + h * 32 + 4);
                ull w0 = __double_as_longlong(wa.x), w1 = __double_as_longlong(wa.y);
                ull w2 = __double_as_longlong(wb2.x), w3 = __double_as_longlong(wb2.y);
                FMA2(vo[0][0], v0, w0); FMA2(vo[0][1], v0, w1); FMA2(vo[0][2], v0, w2); FMA2(vo[0][3], v0, w3);
                FMA2(vo[1][0], v1, w0); FMA2(vo[1][1], v1, w1); FMA2(vo[1][2], v1, w2); FMA2(vo[1][3], v1, w3);
                FMA2(vo[2][0], v2, w0); FMA2(vo[2][1], v2, w1); FMA2(vo[2][2], v2, w2); FMA2(vo[2][3], v2, w3);
            }
        }
    }
    __syncthreads();   // all xs/vnp/vhs readers done

    if (warp < 8) {
        // sigmoids -> xs cols 0..127 (item-scattered, conflict-free: 8b+a banks)
        int itile = (warp & 3) * 16, n0base = (warp >> 2) * 64;
        int tg = lane >> 2, tq = lane & 3;
        #pragma unroll
        for (int nt = 0; nt < 8; nt++) {
            int o = n0base + nt * 8 + 2 * tq;
            int i_lo = itile + tg, i_hi = i_lo + 8;
            xs[o * 68 + i_lo]       = sg[nt][0];
            xs[(o + 1) * 68 + i_lo] = sg[nt][1];
            xs[o * 68 + i_hi]       = sg[nt][2];
            xs[(o + 1) * 68 + i_hi] = sg[nt][3];
        }
    }
    __syncthreads();   // sig visible

    // ---- gate: thread = 1 item x 4 m
    {
        int j = tid & 7, ig = tid >> 3;
        ull ga[2] = {};
        const float* wrow = wsv + j * 4;
        #pragma unroll 4
        for (int o = 0; o < 128; o++) {
            ull xp = packx2(xs[o * 68 + ig]);
            double2 wd = *(const double2*)(wrow + o * 32);
            FMA2(ga[0], xp, __double_as_longlong(wd.x));
            FMA2(ga[1], xp, __double_as_longlong(wd.y));
        }
        float2 f0 = unpk(ga[0]), f1 = unpk(ga[1]);
        gsb[ig * 33 + j * 4 + 0] = sigf(f0.x + svb[j * 4 + 0]);
        gsb[ig * 33 + j * 4 + 1] = sigf(f0.y + svb[j * 4 + 1]);
        gsb[ig * 33 + j * 4 + 2] = sigf(f1.x + svb[j * 4 + 2]);
        gsb[ig * 33 + j * 4 + 3] = sigf(f1.y + svb[j * 4 + 3]);
    }
    __syncthreads();   // gsb visible

    if (warp >= 8) {
        int t2 = tid - 256;
        int i = t2 & 63, mg = t2 >> 6;
        #pragma unroll
        for (int mp = 0; mp < 4; mp++) {
            int m0 = mg * 8 + 2 * mp;
            float g0 = gsb[i * 33 + m0], g1 = gsb[i * 33 + m0 + 1];
            #pragma unroll
            for (int d = 0; d < 3; d++) {
                float2 fr = unpk(vo[d][mp]);
                vhs[i * 97 + m0 * 3 + d]       = fr.x * g0;
                vhs[i * 97 + (m0 + 1) * 3 + d] = fr.y * g1;
            }
        }
        asm volatile("bar.sync 1, 256;" ::: "memory");
        int wi = warp - 8;
        for (int ii = 0; ii < 8; ii++) {
            int item = wi * 8 + ii;
            size_t gb2 = (size_t)(base + item) * 224;
            #pragma unroll
            for (int q = 0; q < 3; q++) {
                int l = lane + 32 * q;
                int m = l / 3, d = l - m * 3;
                int gpos = (m >> 3) * 56 + 32 + (m & 7) * 3 + d;
                g_q[gb2 + gpos] = vhs[item * 97 + l];
            }
        }
    }
}

// ---- K2a ----
__global__ void __launch_bounds__(256) k2a_stats() {
    __shared__ float redm[8 * 33], reds[8 * 33];
    int seg = blockIdx.x, c = blockIdx.y;
    int t = threadIdx.x, a = t & 31, part = t >> 5;
    float m = -3.4e38f, sum = 0.f;
    int nb = seg * 512 + part * 64;
    for (int i = 0; i < 64; i++) {
        float val = g_logits[((size_t)(nb + i) * C_DIM + c) * 32 + a];
        float nm = fmaxf(m, val);
        sum = sum * __expf(m - nm) + __expf(val - nm);
        m = nm;
    }
    redm[part * 33 + a] = m; reds[part * 33 + a] = sum;
    __syncthreads();
    if (t < 32) {
        float mm = redm[t], ss = reds[t];
        #pragma unroll
        for (int p = 1; p < 8; p++) {
            float m2 = redm[p * 33 + t], s2 = reds[p * 33 + t];
            float nm = fmaxf(mm, m2);
            ss = ss * __expf(mm - nm) + s2 * __expf(m2 - nm);
            mm = nm;
        }
        g_pm[(c * 16 + seg) * 32 + t] = mm;
        g_ps[(c * 16 + seg) * 32 + t] = ss;
    }
}

// ---- K3 (R8 single-buffer, inline stat merge) ----
__global__ void __launch_bounds__(224) k3_compress(const float* __restrict__ s,
                                                   const float* __restrict__ v) {
    __shared__ float xt[32 * 226];
    __shared__ float wt[32 * 33];
    __shared__ float mloc[32], iloc[32];
    int t = threadIdx.x;
    int chunk = blockIdx.x, c = blockIdx.y;
    if (t < 32) {
        float m = -3.4e38f;
        #pragma unroll
        for (int sg2 = 0; sg2 < 16; sg2++) m = fmaxf(m, g_pm[(c * 16 + sg2) * 32 + t]);
        float sum = 0.f;
        #pragma unroll
        for (int sg2 = 0; sg2 < 16; sg2++)
            sum += g_ps[(c * 16 + sg2) * 32 + t] * __expf(g_pm[(c * 16 + sg2) * 32 + t] - m);
        mloc[t] = m; iloc[t] = 1.0f / sum;
    }
    int a0 = (t & 7) * 4, j0 = (t >> 3) * 8;
    ull acc[4][4] = {};
    for (int sub = 0; sub < 4; sub++) {
        __syncthreads();
        #pragma unroll 4
        for (int n = 0; n < 32; n++) {
            int item = (chunk * 128 + sub * 32 + n) * C_DIM + c;
            xt[n * 226 + t] = (t < 128) ? s[(size_t)item * 128 + t]
                                        : v[(size_t)item * 96 + (t - 128)];
        }
        for (int idx = t; idx < 1024; idx += 224) {
            int n = idx >> 5, a = idx & 31;
            int item = (chunk * 128 + sub * 32 + n) * C_DIM + c;
            wt[n * 33 + a] = __expf(g_logits[(size_t)item * 32 + a] - mloc[a]) * iloc[a];
        }
        __syncthreads();
        #pragma unroll 4
        for (int n = 0; n < 32; n++) {
            ull wpk[4];
            #pragma unroll
            for (int u = 0; u < 4; u++) wpk[u] = packx2(wt[n * 33 + a0 + u]);
            const ull* x2 = (const ull*)(xt + n * 226 + j0);
            #pragma unroll
            for (int vv = 0; vv < 4; vv++) {
                ull xp = x2[vv];
                FMA2(acc[0][vv], wpk[0], xp);
                FMA2(acc[1][vv], wpk[1], xp);
                FMA2(acc[2][vv], wpk[2], xp);
                FMA2(acc[3][vv], wpk[3], xp);
            }
        }
    }
    #pragma unroll
    for (int u = 0; u < 4; u++) {
        size_t basep = ((size_t)(chunk * C_DIM + c) * 32 + a0 + u) * 224 + j0;
        #pragma unroll
        for (int vv = 0; vv < 4; vv++) {
            float2 fr = unpk(acc[u][vv]);
            *(float2*)&g_part[basep + 2 * vv] = fr;
        }
    }
}

// ---- K4 ----
__global__ void k4_reduce() {
    int bx = blockIdx.x; int c = bx >> 5, a = bx & 31; int t = threadIdx.x;
    float sum = 0.f;
    for (int ch = 0; ch < NCHUNK; ++ch)
        sum += g_part[((size_t)(ch * C_DIM + c) * 32 + a) * 224 + t];
    g_gbuf[(a * C_DIM + c) * 224 + t] = sum;
}

// ---- K5 ----
__global__ void k5_globals(
    const float* __restrict__ k_wh, const float* __restrict__ k_ws_w, const float* __restrict__ k_ws_b,
    const float* __restrict__ k_wv, const float* __restrict__ k_wsv_w, const float* __restrict__ k_wsv_b,
    const float* __restrict__ p_wh, const float* __restrict__ p_ws_w, const float* __restrict__ p_ws_b,
    const float* __restrict__ p_wv, const float* __restrict__ p_wsv_w, const float* __restrict__ p_wsv_b) {
    __shared__ float wx[8][608];
    int tid = threadIdx.x, warp = tid >> 5, lane = tid & 31;
    int w = blockIdx.x * 8 + warp;
    int which = w >> 9, item = w & 511;
    const float* wh   = which ? p_wh    : k_wh;
    const float* wsw  = which ? p_ws_w  : k_ws_w;
    const float* wsb  = which ? p_ws_b  : k_ws_b;
    const float* wv   = which ? p_wv    : k_wv;
    const float* wsvw = which ? p_wsv_w : k_wsv_w;
    const float* wsvb = which ? p_wsv_b : k_wsv_b;
    float* x = wx[warp]; float* vhsl = x + 224; float* vns = x + 320; float* sig = x + 480;
    const float* gp = &g_gbuf[item * 224];
    #pragma unroll
    for (int k = 0; k < 7; k++) x[lane + 32 * k] = gp[lane + 32 * k];
    __syncwarp();
    float a0 = 0.f, a1 = 0.f, a2 = 0.f;
    #pragma unroll
    for (int i = 0; i < 32; i++) {
        float ww = __ldg(&wh[lane * 32 + i]);
        a0 = fmaf(x[128 + i * 3 + 0], ww, a0);
        a1 = fmaf(x[128 + i * 3 + 1], ww, a1);
        a2 = fmaf(x[128 + i * 3 + 2], ww, a2);
    }
    vhsl[lane] = a0; vhsl[32 + lane] = a1; vhsl[64 + lane] = a2;
    vns[lane] = sqrtf(fmaxf(a0 * a0 + a1 * a1 + a2 * a2, 1e-8f));
    __syncwarp();
    float so[4];
    #pragma unroll
    for (int k = 0; k < 4; k++) {
        int o = lane + 32 * k;
        float acc = __ldg(&wsb[o]);
        const float* wr = &wsw[o * 160];
        #pragma unroll
        for (int j = 0; j < 128; j++) acc = fmaf(x[j], __ldg(&wr[j]), acc);
        #pragma unroll
        for (int j = 0; j < 32; j++) acc = fmaf(vns[j], __ldg(&wr[128 + j]), acc);
        so[k] = acc;
        sig[o] = sigf(acc);
    }
    __syncwarp();
    float g = __ldg(&wsvb[lane]);
    #pragma unroll
    for (int j = 0; j < 128; j++) g = fmaf(sig[j], __ldg(&wsvw[lane * 128 + j]), g);
    float gs = sigf(g);
    float* outp = which ? g_ve : g_ke;
    int a = item >> 4, cc = item & 15;
    size_t ob = ((size_t)cc * 32 + a) * 224;
    int h = lane >> 3;
    int vpos = h * 56 + 32 + (lane & 7) * 3;
    #pragma unroll
    for (int d = 0; d < 3; d++) {
        float vo = 0.f;
        #pragma unroll
        for (int hh = 0; hh < 32; hh++) vo = fmaf(vhsl[d * 32 + hh], __ldg(&wv[lane * 32 + hh]), vo);
        outp[ob + vpos + d] = vo * gs;
    }
    #pragma unroll
    for (int k = 0; k < 4; k++) { int o = lane + 32 * k; outp[ob + k * 56 + lane] = so[k] * sig[o]; }
}

// ---- KB: attention, 32 items x 1 channel, 256 threads ----
__global__ void __launch_bounds__(256) kb_attn(float* __restrict__ out) {
    extern __shared__ float sm[];
    float* qe  = sm;            // [224][33]
    float* keT = sm + 7392;     // [224][34]
    float* ve  = sm + 15008;    // [32][226]
    float* al  = sm + 22240;    // [32][133]
    int tid = threadIdx.x;
    int c = blockIdx.y;
    int nb = blockIdx.x * 32;

    for (int idx = tid; idx < 32 * 224; idx += 256) {
        int i = idx / 224, pos = idx - i * 224;
        size_t git = (size_t)(nb + i) * 16 + c;
        qe[pos * 33 + i] = g_q[git * 224 + pos];
    }
    for (int idx = tid; idx < 32 * 224; idx += 256) {
        int r = idx / 224, pos = idx - r * 224;
        size_t gb = ((size_t)c * 32 + r) * 224 + pos;
        keT[pos * 34 + r] = g_ke[gb];
        ve[r * 226 + pos] = g_ve[gb];
    }
    __syncthreads();

    int h = tid >> 6, rem = tid & 63;

    {
        int ig = rem >> 3, rg = rem & 7;
        ull acc[4][2] = {};
        #pragma unroll 2
        for (int k = 0; k < 56; k++) {
            int row = h * 56 + k;
            ull qp[4];
            #pragma unroll
            for (int e = 0; e < 4; e++) qp[e] = packx2(qe[row * 33 + ig * 4 + e]);
            const ull* k2 = (const ull*)(keT + row * 34 + rg * 4);
            #pragma unroll
            for (int u = 0; u < 2; u++) {
                ull kp = k2[u];
                FMA2(acc[0][u], qp[0], kp);
                FMA2(acc[1][u], qp[1], kp);
                FMA2(acc[2][u], qp[2], kp);
                FMA2(acc[3][u], qp[3], kp);
            }
        }
        #pragma unroll
        for (int e = 0; e < 4; e++)
            #pragma unroll
            for (int u = 0; u < 2; u++) {
                float2 fr = unpk(acc[e][u]);
                al[(ig * 4 + e) * 133 + h * 33 + rg * 4 + 2 * u]     = fr.x * ESCALE;
                al[(ig * 4 + e) * 133 + h * 33 + rg * 4 + 2 * u + 1] = fr.y * ESCALE;
            }
    }
    __syncthreads();

    if (tid < 128) {
        int i = tid >> 2, h2 = tid & 3;
        float* row = &al[i * 133 + h2 * 33];
        float ev[32], mx = -3.4e38f;
        #pragma unroll
        for (int k = 0; k < 32; k++) { ev[k] = row[k]; mx = fmaxf(mx, ev[k]); }
        float sum = 0.f;
        #pragma unroll
        for (int k = 0; k < 32; k++) { ev[k] = __expf(ev[k] - mx); sum += ev[k]; }
        float inv = 1.0f / sum;
        #pragma unroll
        for (int k = 0; k < 32; k++) row[k] = ev[k] * inv;
    }
    __syncthreads();

    {
        int ig = rem >> 2, j = rem & 3;
        ull accs[2][4] = {};
        ull accv[2][3] = {};
        #pragma unroll 2
        for (int r = 0; r < 32; r++) {
            ull ap[2];
            #pragma unroll
            for (int e = 0; e < 2; e++) ap[e] = packx2(al[(ig * 2 + e) * 133 + h * 33 + r]);
            const ull* vs2 = (const ull*)(ve + r * 226 + h * 56 + j * 8);
            const ull* vv2 = (const ull*)(ve + r * 226 + h * 56 + 32 + j * 6);
            #pragma unroll
            for (int u = 0; u < 4; u++) {
                ull vp = vs2[u];
                FMA2(accs[0][u], ap[0], vp);
                FMA2(accs[1][u], ap[1], vp);
            }
            #pragma unroll
            for (int u = 0; u < 3; u++) {
                ull vp = vv2[u];
                FMA2(accv[0][u], ap[0], vp);
                FMA2(accv[1][u], ap[1], vp);
            }
        }
        #pragma unroll
        for (int e = 0; e < 2; e++) {
            size_t git = (size_t)(nb + ig * 2 + e) * 16 + c;
            float* ds = &out[git * 128 + h * 32 + j * 8];
            #pragma unroll
            for (int u = 0; u < 4; u++) *(float2*)&ds[2 * u] = unpk(accs[e][u]);
            float* dv = &out[(size_t)NC_ITEMS * 128 + git * 96 + h * 24 + j * 6];
            #pragma unroll
            for (int u = 0; u < 3; u++) *(float2*)&dv[2 * u] = unpk(accv[e][u]);
        }
    }
}

// ============================================================
extern "C" void kernel_launch(void* const* d_in, const int* in_sizes, int n_in,
                              void* d_out, int out_size) {
    (void)in_sizes; (void)n_in; (void)out_size;
    const float* s       = (const float*)d_in[0];
    const float* v       = (const float*)d_in[1];
    const float* wp_wh   = (const float*)d_in[2];
    const float* wp_ws_w = (const float*)d_in[3];
    const float* wp_ws_b = (const float*)d_in[4];
    const float* q_wh    = (const float*)d_in[5];
    const float* q_ws_w  = (const float*)d_in[6];
    const float* q_ws_b  = (const float*)d_in[7];
    const float* q_wv    = (const float*)d_in[8];
    const float* q_wsv_w = (const float*)d_in[9];
    const float* q_wsv_b = (const float*)d_in[10];
    const float* k_wh    = (const float*)d_in[11];
    const float* k_ws_w  = (const float*)d_in[12];
    const float* k_ws_b  = (const float*)d_in[13];
    const float* k_wv    = (const float*)d_in[14];
    const float* k_wsv_w = (const float*)d_in[15];
    const float* k_wsv_b = (const float*)d_in[16];
    const float* vp_wh   = (const float*)d_in[17];
    const float* vp_ws_w = (const float*)d_in[18];
    const float* vp_ws_b = (const float*)d_in[19];
    const float* vp_wv   = (const float*)d_in[20];
    const float* vp_wsv_w= (const float*)d_in[21];
    const float* vp_wsv_b= (const float*)d_in[22];
    float* out = (float*)d_out;

    cudaFuncSetAttribute((const void*)ka_gvp,  cudaFuncAttributeMaxDynamicSharedMemorySize, KA_SMEMF * 4);
    cudaFuncSetAttribute((const void*)kb_attn, cudaFuncAttributeMaxDynamicSharedMemorySize, 26496 * 4);

    kz<<<1, 32>>>();
    k0b<<<20, 256>>>(wp_ws_w);
    k0c<<<16, 256>>>(q_wsv_w);
    ka_gvp<<<2048, 512, KA_SMEMF * 4>>>(s, v, q_wh, q_ws_w, q_ws_b, q_wv,
                                        q_wsv_b, wp_wh, wp_ws_b);   // 4th -> profiled
    k2a_stats<<<dim3(16, 16), 256>>>();
    k3_compress<<<dim3(NCHUNK, C_DIM), 224>>>(s, v);
    k4_reduce<<<512, 224>>>();
    k5_globals<<<128, 256>>>(k_wh, k_ws_w, k_ws_b, k_wv, k_wsv_w, k_wsv_b,
                             vp_wh, vp_ws_w, vp_ws_b, vp_wv, vp_wsv_w, vp_wsv_b);
    kb_attn<<<dim3(256, C_DIM), 256, 26496 * 4>>>(out);
}

// round 13
// speedup vs baseline: 1.1920x; 1.0985x over previous
#include <cuda_runtime.h>

#define N_NODES 8192
#define C_DIM   16
#define NC_ITEMS (N_NODES * C_DIM)
#define R_ANCH  32
#define XD      224
#define NCHUNK  64
#define ESCALE  0.15811388300841898f

typedef unsigned long long ull;
typedef unsigned int uint;

__device__ float g_logits[NC_ITEMS * R_ANCH];
__device__ float g_pm[C_DIM * 16 * R_ANCH];
__device__ float g_ps[C_DIM * 16 * R_ANCH];
__device__ float g_part[NCHUNK * C_DIM * R_ANCH * XD];
__device__ float g_gbuf[R_ANCH * C_DIM * XD];
__device__ float g_ke[C_DIM * R_ANCH * XD];
__device__ float g_ve[C_DIM * R_ANCH * XD];
__device__ float g_q[(size_t)NC_ITEMS * XD];
__device__ float g_wpT[160 * 32];
__device__ float g_wsvT[128 * 32];

__device__ __forceinline__ float sigf(float x) { return 1.0f / (1.0f + __expf(-x)); }
#define FMA2(d, a, b) asm("fma.rn.f32x2 %0, %1, %2, %0;" : "+l"(d) : "l"(a), "l"(b))
__device__ __forceinline__ ull packx2(float x) {
    ull o; unsigned r = __float_as_uint(x);
    asm("mov.b64 %0, {%1, %1};" : "=l"(o) : "r"(r));
    return o;
}
__device__ __forceinline__ float2 unpk(ull u) {
    float2 f;
    asm("mov.b64 {%0, %1}, %2;" : "=f"(f.x), "=f"(f.y) : "l"(u));
    return f;
}
__device__ __forceinline__ uint tf32c(float f) {
    uint u;
    asm("cvt.rna.tf32.f32 %0, %1;" : "=r"(u) : "f"(f));
    return u;
}
#define MMA_TF32(d, a0, a1, a2, a3, b0, b1) \
    asm volatile("mma.sync.aligned.m16n8k8.row.col.f32.tf32.tf32.f32 " \
        "{%0,%1,%2,%3}, {%4,%5,%6,%7}, {%8,%9}, {%0,%1,%2,%3};" \
        : "+f"(d[0]), "+f"(d[1]), "+f"(d[2]), "+f"(d[3]) \
        : "r"(a0), "r"(a1), "r"(a2), "r"(a3), "r"(b0), "r"(b1))

__global__ void kz() { if (threadIdx.x == 0) g_pm[0] = 0.f; }
__global__ void k0b(const float* __restrict__ pw) {
    int i = blockIdx.x * 256 + threadIdx.x;
    if (i < 160 * 32) { int k = i >> 5, a = i & 31; g_wpT[i] = pw[a * 160 + k]; }
}
__global__ void k0c(const float* __restrict__ sv) {
    int i = blockIdx.x * 256 + threadIdx.x;
    if (i < 128 * 32) { int k = i >> 5, m = i & 31; g_wsvT[i] = sv[m * 128 + k]; }
}

// ---- ka smem offsets (floats) ----
#define OF_WQOM 0        // [128][164] tf32 bits [o][k]
#define OF_WP   20992    // [160][32] k-major fp32
#define OF_WSVT 26112    // [128][36] tf32 bits [o][m]
#define OF_WHQ  30720
#define OF_WHP  31808
#define OF_WVVT 32896
#define OF_SBQ  33920
#define OF_SBP  34048
#define OF_SVB  34080
#define OF_XS   34112    // [160][68]
#define OF_VNP  44992    // [32][66]
#define OF_VHS  47104    // [64][97]
#define OF_GSB  53312    // [64][33]
#define OF_VBUF 55424    // [16][104]
#define KA_SMEMF 57088

// ============================================================
// KA: 64 items/block, 512 threads. s_out + gate via tf32 mma.
// ============================================================
__global__ void __launch_bounds__(512) ka_gvp(
    const float* __restrict__ s, const float* __restrict__ v,
    const float* __restrict__ q_wh, const float* __restrict__ q_ws_w,
    const float* __restrict__ q_ws_b, const float* __restrict__ q_wv,
    const float* __restrict__ q_wsv_b,
    const float* __restrict__ wp_wh, const float* __restrict__ wp_ws_b)
{
    extern __shared__ float sm[];
    float* wqom = sm + OF_WQOM;
    float* wp   = sm + OF_WP;
    float* wsvt = sm + OF_WSVT;
    float* whq  = sm + OF_WHQ;
    float* whp  = sm + OF_WHP;
    float* wvvT = sm + OF_WVVT;
    float* sbq  = sm + OF_SBQ;
    float* sbp  = sm + OF_SBP;
    float* svb  = sm + OF_SVB;
    float* xs   = sm + OF_XS;
    float* vnp  = sm + OF_VNP;
    float* vhs  = sm + OF_VHS;
    float* gsb  = sm + OF_GSB;
    float* vbuf = sm + OF_VBUF;

    int tid = threadIdx.x, warp = tid >> 5, lane = tid & 31;
    int base = blockIdx.x * 64;

    for (int i = tid; i < 128 * 160; i += 512) {
        int r = i / 160, c = i - r * 160;
        wqom[r * 164 + c] = __uint_as_float(tf32c(q_ws_w[i]));
    }
    for (int i = tid; i < 5120; i += 512) wp[i] = g_wpT[i];
    for (int i = tid; i < 4096; i += 512) {
        int k = i >> 5, m = i & 31;
        wsvt[k * 36 + m] = __uint_as_float(tf32c(g_wsvT[i]));
    }
    for (int i = tid; i < 1024; i += 512) {
        int r = i >> 5, cc = i & 31;
        whq[r * 34 + cc] = q_wh[i];
        whp[r * 34 + cc] = wp_wh[i];
        wvvT[i] = q_wv[(i & 31) * 32 + (i >> 5)];
    }
    if (tid < 128) sbq[tid] = q_ws_b[tid];
    if (tid < 32)  { sbp[tid] = wp_ws_b[tid]; svb[tid] = q_wsv_b[tid]; }
    __syncthreads();

    // ---- stage A: 16 warps x 4 items
    {
        float* vb = vbuf + warp * 104;
        for (int ii = 0; ii < 4; ii++) {
            int i = warp * 4 + ii;
            size_t git = (size_t)(base + i);
            const float* sp = s + git * 128;
            const float* vpp = v + git * 96;
            #pragma unroll
            for (int k = 0; k < 4; k++) xs[(lane + 32 * k) * 68 + i] = sp[lane + 32 * k];
            #pragma unroll
            for (int k = 0; k < 3; k++) {
                int pos = lane + 32 * k;
                float val = vpp[pos];
                int m = pos / 3, d = pos - m * 3;
                vb[d * 34 + m] = val;
            }
            __syncwarp();
            ull aq0 = 0, aq1 = 0, aq2 = 0, ap0 = 0, ap1 = 0, ap2 = 0;
            #pragma unroll
            for (int m2 = 0; m2 < 32; m2 += 2) {
                ull wqp = *(const ull*)&whq[lane * 34 + m2];
                ull wpp = *(const ull*)&whp[lane * 34 + m2];
                ull v0 = *(const ull*)&vb[m2];
                ull v1 = *(const ull*)&vb[34 + m2];
                ull v2 = *(const ull*)&vb[68 + m2];
                FMA2(aq0, v0, wqp); FMA2(aq1, v1, wqp); FMA2(aq2, v2, wqp);
                FMA2(ap0, v0, wpp); FMA2(ap1, v1, wpp); FMA2(ap2, v2, wpp);
            }
            float2 f;
            f = unpk(aq0); float a0 = f.x + f.y;
            f = unpk(aq1); float a1 = f.x + f.y;
            f = unpk(aq2); float a2 = f.x + f.y;
            f = unpk(ap0); float b0 = f.x + f.y;
            f = unpk(ap1); float b1 = f.x + f.y;
            f = unpk(ap2); float b2 = f.x + f.y;
            vhs[i * 97 + lane] = a0; vhs[i * 97 + 32 + lane] = a1; vhs[i * 97 + 64 + lane] = a2;
            xs[(128 + lane) * 68 + i] = sqrtf(fmaxf(a0 * a0 + a1 * a1 + a2 * a2, 1e-8f));
            vnp[lane * 66 + i]        = sqrtf(fmaxf(b0 * b0 + b1 * b1 + b2 * b2, 1e-8f));
            __syncwarp();
        }
    }
    __syncthreads();

    float sg[8][4];
    ull vo[3][4] = {};

    if (warp < 8) {
        // ---- s_out tf32 mma: warp = 16 items x 64 outs
        int itile = (warp & 3) * 16, n0base = (warp >> 2) * 64;
        int tg = lane >> 2, tq = lane & 3;
        float d[8][4] = {};
        #pragma unroll
        for (int kk = 0; kk < 20; kk++) {
            int kb = kk * 8;
            uint a0 = tf32c(xs[(kb + tq) * 68 + itile + tg]);
            uint a1 = tf32c(xs[(kb + tq) * 68 + itile + tg + 8]);
            uint a2 = tf32c(xs[(kb + tq + 4) * 68 + itile + tg]);
            uint a3 = tf32c(xs[(kb + tq + 4) * 68 + itile + tg + 8]);
            #pragma unroll
            for (int nt = 0; nt < 8; nt++) {
                const float* wb = wqom + (n0base + nt * 8 + tg) * 164 + kb + tq;
                uint b0 = __float_as_uint(wb[0]);
                uint b1 = __float_as_uint(wb[4]);
                MMA_TF32(d[nt], a0, a1, a2, a3, b0, b1);
            }
        }
        #pragma unroll
        for (int nt = 0; nt < 8; nt++) {
            int o = n0base + nt * 8 + 2 * tq;
            float bb0 = sbq[o], bb1 = sbq[o + 1];
            int gp0 = (o >> 5) * 56 + (o & 31);
            int i_lo = itile + tg, i_hi = i_lo + 8;
            float s00 = d[nt][0] + bb0, s01 = d[nt][1] + bb1;
            float s10 = d[nt][2] + bb0, s11 = d[nt][3] + bb1;
            float g00 = sigf(s00), g01 = sigf(s01), g10 = sigf(s10), g11 = sigf(s11);
            sg[nt][0] = g00; sg[nt][1] = g01; sg[nt][2] = g10; sg[nt][3] = g11;
            *(float2*)&g_q[(size_t)(base + i_lo) * 224 + gp0] = make_float2(s00 * g00, s01 * g01);
            *(float2*)&g_q[(size_t)(base + i_hi) * 224 + gp0] = make_float2(s10 * g10, s11 * g11);
        }
    } else {
        int t2 = tid - 256;
        int i = t2 & 63, jg = t2 >> 6;
        // ---- logits fp32
        {
            ull la[4] = {};
            const float* wrow = wp + jg * 8;
            #pragma unroll 2
            for (int k = 0; k < 128; k++) {
                ull xp = packx2(xs[k * 68 + i]);
                double2 wa = *(const double2*)(wrow + k * 32);
                double2 wb2 = *(const double2*)(wrow + k * 32 + 4);
                FMA2(la[0], xp, __double_as_longlong(wa.x));
                FMA2(la[1], xp, __double_as_longlong(wa.y));
                FMA2(la[2], xp, __double_as_longlong(wb2.x));
                FMA2(la[3], xp, __double_as_longlong(wb2.y));
            }
            #pragma unroll 2
            for (int k = 0; k < 32; k++) {
                ull xp = packx2(vnp[k * 66 + i]);
                double2 wa = *(const double2*)(wrow + (128 + k) * 32);
                double2 wb2 = *(const double2*)(wrow + (128 + k) * 32 + 4);
                FMA2(la[0], xp, __double_as_longlong(wa.x));
                FMA2(la[1], xp, __double_as_longlong(wa.y));
                FMA2(la[2], xp, __double_as_longlong(wb2.x));
                FMA2(la[3], xp, __double_as_longlong(wb2.y));
            }
            float2 f0 = unpk(la[0]), f1 = unpk(la[1]), f2 = unpk(la[2]), f3 = unpk(la[3]);
            const float* bp = sbp + jg * 8;
            size_t gl = (size_t)(base + i) * 32 + jg * 8;
            *(float4*)&g_logits[gl]     = make_float4(f0.x + bp[0], f0.y + bp[1], f1.x + bp[2], f1.y + bp[3]);
            *(float4*)&g_logits[gl + 4] = make_float4(f2.x + bp[4], f2.y + bp[5], f3.x + bp[6], f3.y + bp[7]);
        }
        // ---- v_out accumulate (gate deferred)
        {
            const float* wvb = wvvT + jg * 8;
            const float* vr = vhs + i * 97;
            #pragma unroll 2
            for (int h = 0; h < 32; h++) {
                ull v0 = packx2(vr[h]);
                ull v1 = packx2(vr[32 + h]);
                ull v2 = packx2(vr[64 + h]);
                double2 wa = *(const double2*)(wvb + h * 32);
                double2 wb2 = *(const double2*)(wvb + h * 32 + 4);
                ull w0 = __double_as_longlong(wa.x), w1 = __double_as_longlong(wa.y);
                ull w2 = __double_as_longlong(wb2.x), w3 = __double_as_longlong(wb2.y);
                FMA2(vo[0][0], v0, w0); FMA2(vo[0][1], v0, w1); FMA2(vo[0][2], v0, w2); FMA2(vo[0][3], v0, w3);
                FMA2(vo[1][0], v1, w0); FMA2(vo[1][1], v1, w1); FMA2(vo[1][2], v1, w2); FMA2(vo[1][3], v1, w3);
                FMA2(vo[2][0], v2, w0); FMA2(vo[2][1], v2, w1); FMA2(vo[2][2], v2, w2); FMA2(vo[2][3], v2, w3);
            }
        }
    }
    __syncthreads();

    if (warp < 8) {
        int itile = (warp & 3) * 16, n0base = (warp >> 2) * 64;
        int tg = lane >> 2, tq = lane & 3;
        #pragma unroll
        for (int nt = 0; nt < 8; nt++) {
            int o = n0base + nt * 8 + 2 * tq;
            int i_lo = itile + tg, i_hi = i_lo + 8;
            xs[o * 68 + i_lo]       = sg[nt][0];
            xs[(o + 1) * 68 + i_lo] = sg[nt][1];
            xs[o * 68 + i_hi]       = sg[nt][2];
            xs[(o + 1) * 68 + i_hi] = sg[nt][3];
        }
    }
    __syncthreads();   // sig visible

    if (warp < 4) {
        // ---- gate tf32 mma: warp = 16 items x 32 m
        int itile = warp * 16;
        int tg = lane >> 2, tq = lane & 3;
        float d[4][4] = {};
        #pragma unroll
        for (int kk = 0; kk < 16; kk++) {
            int kb = kk * 8;
            uint a0 = tf32c(xs[(kb + tq) * 68 + itile + tg]);
            uint a1 = tf32c(xs[(kb + tq) * 68 + itile + tg + 8]);
            uint a2 = tf32c(xs[(kb + tq + 4) * 68 + itile + tg]);
            uint a3 = tf32c(xs[(kb + tq + 4) * 68 + itile + tg + 8]);
            #pragma unroll
            for (int nt = 0; nt < 4; nt++) {
                uint b0 = __float_as_uint(wsvt[(kb + tq) * 36 + nt * 8 + tg]);
                uint b1 = __float_as_uint(wsvt[(kb + tq + 4) * 36 + nt * 8 + tg]);
                MMA_TF32(d[nt], a0, a1, a2, a3, b0, b1);
            }
        }
        #pragma unroll
        for (int nt = 0; nt < 4; nt++) {
            int m = nt * 8 + 2 * tq;
            float b0 = svb[m], b1 = svb[m + 1];
            int i_lo = itile + tg, i_hi = i_lo + 8;
            gsb[i_lo * 33 + m]     = sigf(d[nt][0] + b0);
            gsb[i_lo * 33 + m + 1] = sigf(d[nt][1] + b1);
            gsb[i_hi * 33 + m]     = sigf(d[nt][2] + b0);
            gsb[i_hi * 33 + m + 1] = sigf(d[nt][3] + b1);
        }
    }
    __syncthreads();   // gsb visible

    if (warp >= 8) {
        int t2 = tid - 256;
        int i = t2 & 63, mg = t2 >> 6;
        #pragma unroll
        for (int mp = 0; mp < 4; mp++) {
            int m0 = mg * 8 + 2 * mp;
            float g0 = gsb[i * 33 + m0], g1 = gsb[i * 33 + m0 + 1];
            #pragma unroll
            for (int d = 0; d < 3; d++) {
                float2 fr = unpk(vo[d][mp]);
                vhs[i * 97 + m0 * 3 + d]       = fr.x * g0;
                vhs[i * 97 + (m0 + 1) * 3 + d] = fr.y * g1;
            }
        }
        asm volatile("bar.sync 1, 256;" ::: "memory");
        int wi = warp - 8;
        for (int ii = 0; ii < 8; ii++) {
            int item = wi * 8 + ii;
            size_t gb2 = (size_t)(base + item) * 224;
            #pragma unroll
            for (int q = 0; q < 3; q++) {
                int l = lane + 32 * q;
                int m = l / 3, d = l - m * 3;
                int gpos = (m >> 3) * 56 + 32 + (m & 7) * 3 + d;
                g_q[gb2 + gpos] = vhs[item * 97 + l];
            }
        }
    }
}

// ---- K2a ----
__global__ void __launch_bounds__(256) k2a_stats() {
    __shared__ float redm[8 * 33], reds[8 * 33];
    int seg = blockIdx.x, c = blockIdx.y;
    int t = threadIdx.x, a = t & 31, part = t >> 5;
    float m = -3.4e38f, sum = 0.f;
    int nb = seg * 512 + part * 64;
    for (int i = 0; i < 64; i++) {
        float val = g_logits[((size_t)(nb + i) * C_DIM + c) * 32 + a];
        float nm = fmaxf(m, val);
        sum = sum * __expf(m - nm) + __expf(val - nm);
        m = nm;
    }
    redm[part * 33 + a] = m; reds[part * 33 + a] = sum;
    __syncthreads();
    if (t < 32) {
        float mm = redm[t], ss = reds[t];
        #pragma unroll
        for (int p = 1; p < 8; p++) {
            float m2 = redm[p * 33 + t], s2 = reds[p * 33 + t];
            float nm = fmaxf(mm, m2);
            ss = ss * __expf(mm - nm) + s2 * __expf(m2 - nm);
            mm = nm;
        }
        g_pm[(c * 16 + seg) * 32 + t] = mm;
        g_ps[(c * 16 + seg) * 32 + t] = ss;
    }
}

// ---- K3 ----
__global__ void __launch_bounds__(224) k3_compress(const float* __restrict__ s,
                                                   const float* __restrict__ v) {
    __shared__ float xt[32 * 226];
    __shared__ float wt[32 * 33];
    __shared__ float mloc[32], iloc[32];
    int t = threadIdx.x;
    int chunk = blockIdx.x, c = blockIdx.y;
    if (t < 32) {
        float m = -3.4e38f;
        #pragma unroll
        for (int sg2 = 0; sg2 < 16; sg2++) m = fmaxf(m, g_pm[(c * 16 + sg2) * 32 + t]);
        float sum = 0.f;
        #pragma unroll
        for (int sg2 = 0; sg2 < 16; sg2++)
            sum += g_ps[(c * 16 + sg2) * 32 + t] * __expf(g_pm[(c * 16 + sg2) * 32 + t] - m);
        mloc[t] = m; iloc[t] = 1.0f / sum;
    }
    int a0 = (t & 7) * 4, j0 = (t >> 3) * 8;
    ull acc[4][4] = {};
    for (int sub = 0; sub < 4; sub++) {
        __syncthreads();
        #pragma unroll 4
        for (int n = 0; n < 32; n++) {
            int item = (chunk * 128 + sub * 32 + n) * C_DIM + c;
            xt[n * 226 + t] = (t < 128) ? s[(size_t)item * 128 + t]
                                        : v[(size_t)item * 96 + (t - 128)];
        }
        for (int idx = t; idx < 1024; idx += 224) {
            int n = idx >> 5, a = idx & 31;
            int item = (chunk * 128 + sub * 32 + n) * C_DIM + c;
            wt[n * 33 + a] = __expf(g_logits[(size_t)item * 32 + a] - mloc[a]) * iloc[a];
        }
        __syncthreads();
        #pragma unroll 4
        for (int n = 0; n < 32; n++) {
            ull wpk[4];
            #pragma unroll
            for (int u = 0; u < 4; u++) wpk[u] = packx2(wt[n * 33 + a0 + u]);
            const ull* x2 = (const ull*)(xt + n * 226 + j0);
            #pragma unroll
            for (int vv = 0; vv < 4; vv++) {
                ull xp = x2[vv];
                FMA2(acc[0][vv], wpk[0], xp);
                FMA2(acc[1][vv], wpk[1], xp);
                FMA2(acc[2][vv], wpk[2], xp);
                FMA2(acc[3][vv], wpk[3], xp);
            }
        }
    }
    #pragma unroll
    for (int u = 0; u < 4; u++) {
        size_t basep = ((size_t)(chunk * C_DIM + c) * 32 + a0 + u) * 224 + j0;
        #pragma unroll
        for (int vv = 0; vv < 4; vv++) {
            float2 fr = unpk(acc[u][vv]);
            *(float2*)&g_part[basep + 2 * vv] = fr;
        }
    }
}

// ---- K4 ----
__global__ void k4_reduce() {
    int bx = blockIdx.x; int c = bx >> 5, a = bx & 31; int t = threadIdx.x;
    float sum = 0.f;
    for (int ch = 0; ch < NCHUNK; ++ch)
        sum += g_part[((size_t)(ch * C_DIM + c) * 32 + a) * 224 + t];
    g_gbuf[(a * C_DIM + c) * 224 + t] = sum;
}

// ---- K5 ----
__global__ void k5_globals(
    const float* __restrict__ k_wh, const float* __restrict__ k_ws_w, const float* __restrict__ k_ws_b,
    const float* __restrict__ k_wv, const float* __restrict__ k_wsv_w, const float* __restrict__ k_wsv_b,
    const float* __restrict__ p_wh, const float* __restrict__ p_ws_w, const float* __restrict__ p_ws_b,
    const float* __restrict__ p_wv, const float* __restrict__ p_wsv_w, const float* __restrict__ p_wsv_b) {
    __shared__ float wx[8][608];
    int tid = threadIdx.x, warp = tid >> 5, lane = tid & 31;
    int w = blockIdx.x * 8 + warp;
    int which = w >> 9, item = w & 511;
    const float* wh   = which ? p_wh    : k_wh;
    const float* wsw  = which ? p_ws_w  : k_ws_w;
    const float* wsb  = which ? p_ws_b  : k_ws_b;
    const float* wv   = which ? p_wv    : k_wv;
    const float* wsvw = which ? p_wsv_w : k_wsv_w;
    const float* wsvb = which ? p_wsv_b : k_wsv_b;
    float* x = wx[warp]; float* vhsl = x + 224; float* vns = x + 320; float* sig = x + 480;
    const float* gp = &g_gbuf[item * 224];
    #pragma unroll
    for (int k = 0; k < 7; k++) x[lane + 32 * k] = gp[lane + 32 * k];
    __syncwarp();
    float a0 = 0.f, a1 = 0.f, a2 = 0.f;
    #pragma unroll
    for (int i = 0; i < 32; i++) {
        float ww = __ldg(&wh[lane * 32 + i]);
        a0 = fmaf(x[128 + i * 3 + 0], ww, a0);
        a1 = fmaf(x[128 + i * 3 + 1], ww, a1);
        a2 = fmaf(x[128 + i * 3 + 2], ww, a2);
    }
    vhsl[lane] = a0; vhsl[32 + lane] = a1; vhsl[64 + lane] = a2;
    vns[lane] = sqrtf(fmaxf(a0 * a0 + a1 * a1 + a2 * a2, 1e-8f));
    __syncwarp();
    float so[4];
    #pragma unroll
    for (int k = 0; k < 4; k++) {
        int o = lane + 32 * k;
        float acc = __ldg(&wsb[o]);
        const float* wr = &wsw[o * 160];
        #pragma unroll
        for (int j = 0; j < 128; j++) acc = fmaf(x[j], __ldg(&wr[j]), acc);
        #pragma unroll
        for (int j = 0; j < 32; j++) acc = fmaf(vns[j], __ldg(&wr[128 + j]), acc);
        so[k] = acc;
        sig[o] = sigf(acc);
    }
    __syncwarp();
    float g = __ldg(&wsvb[lane]);
    #pragma unroll
    for (int j = 0; j < 128; j++) g = fmaf(sig[j], __ldg(&wsvw[lane * 128 + j]), g);
    float gs = sigf(g);
    float* outp = which ? g_ve : g_ke;
    int a = item >> 4, cc = item & 15;
    size_t ob = ((size_t)cc * 32 + a) * 224;
    int h = lane >> 3;
    int vpos = h * 56 + 32 + (lane & 7) * 3;
    #pragma unroll
    for (int d = 0; d < 3; d++) {
        float vo = 0.f;
        #pragma unroll
        for (int hh = 0; hh < 32; hh++) vo = fmaf(vhsl[d * 32 + hh], __ldg(&wv[lane * 32 + hh]), vo);
        outp[ob + vpos + d] = vo * gs;
    }
    #pragma unroll
    for (int k = 0; k < 4; k++) { int o = lane + 32 * k; outp[ob + k * 56 + lane] = so[k] * sig[o]; }
}

// ============================================================
// KB: attention via tf32 mma. 32 items x 1 channel, 256 threads.
// ============================================================
__global__ void __launch_bounds__(256) kb_attn(float* __restrict__ out) {
    extern __shared__ float sm[];
    float* qe  = sm;            // [224][33] tf32 bits
    float* keT = sm + 7392;     // [224][34] tf32 bits
    float* ve  = sm + 15008;    // [32][226] fp32
    float* al  = sm + 22240;    // [32][133] fp32
    int tid = threadIdx.x;
    int c = blockIdx.y;
    int nb = blockIdx.x * 32;

    for (int idx = tid; idx < 32 * 224; idx += 256) {
        int i = idx / 224, pos = idx - i * 224;
        size_t git = (size_t)(nb + i) * 16 + c;
        qe[pos * 33 + i] = __uint_as_float(tf32c(g_q[git * 224 + pos]));
    }
    for (int idx = tid; idx < 32 * 224; idx += 256) {
        int r = idx / 224, pos = idx - r * 224;
        size_t gb = ((size_t)c * 32 + r) * 224 + pos;
        keT[pos * 34 + r] = __uint_as_float(tf32c(g_ke[gb]));
        ve[r * 226 + pos] = g_ve[gb];
    }
    __syncthreads();

    int warp = tid >> 5, lane = tid & 31;
    int h = warp >> 1, mt = warp & 1;
    int it0 = mt * 16;
    int tg = lane >> 2, tq = lane & 3;

    // ---- energy mma: warp = (h, 16 items) x 32 anchors, k=56
    {
        float d[4][4] = {};
        #pragma unroll
        for (int kk = 0; kk < 7; kk++) {
            int kbase = h * 56 + kk * 8;
            uint a0 = __float_as_uint(qe[(kbase + tq) * 33 + it0 + tg]);
            uint a1 = __float_as_uint(qe[(kbase + tq) * 33 + it0 + tg + 8]);
            uint a2 = __float_as_uint(qe[(kbase + tq + 4) * 33 + it0 + tg]);
            uint a3 = __float_as_uint(qe[(kbase + tq + 4) * 33 + it0 + tg + 8]);
            #pragma unroll
            for (int nt = 0; nt < 4; nt++) {
                uint b0 = __float_as_uint(keT[(kbase + tq) * 34 + nt * 8 + tg]);
                uint b1 = __float_as_uint(keT[(kbase + tq + 4) * 34 + nt * 8 + tg]);
                MMA_TF32(d[nt], a0, a1, a2, a3, b0, b1);
            }
        }
        #pragma unroll
        for (int nt = 0; nt < 4; nt++) {
            int a = nt * 8 + 2 * tq;
            int i_lo = it0 + tg, i_hi = i_lo + 8;
            al[i_lo * 133 + h * 33 + a]     = d[nt][0] * ESCALE;
            al[i_lo * 133 + h * 33 + a + 1] = d[nt][1] * ESCALE;
            al[i_hi * 133 + h * 33 + a]     = d[nt][2] * ESCALE;
            al[i_hi * 133 + h * 33 + a + 1] = d[nt][3] * ESCALE;
        }
    }
    __syncthreads();

    // ---- softmax over anchors: thread per (item, head)
    if (tid < 128) {
        int i = tid >> 2, h2 = tid & 3;
        float* row = &al[i * 133 + h2 * 33];
        float ev[32], mx = -3.4e38f;
        #pragma unroll
        for (int k = 0; k < 32; k++) { ev[k] = row[k]; mx = fmaxf(mx, ev[k]); }
        float sum = 0.f;
        #pragma unroll
        for (int k = 0; k < 32; k++) { ev[k] = __expf(ev[k] - mx); sum += ev[k]; }
        float inv = 1.0f / sum;
        #pragma unroll
        for (int k = 0; k < 32; k++) row[k] = ev[k] * inv;
    }
    __syncthreads();

    // ---- out mma: warp = (h, 16 items) x 56 pos, k=32 anchors
    {
        float d2[7][4] = {};
        #pragma unroll
        for (int kk = 0; kk < 4; kk++) {
            int kb = kk * 8;
            uint a0 = tf32c(al[(it0 + tg) * 133 + h * 33 + kb + tq]);
            uint a1 = tf32c(al[(it0 + tg + 8) * 133 + h * 33 + kb + tq]);
            uint a2 = tf32c(al[(it0 + tg) * 133 + h * 33 + kb + tq + 4]);
            uint a3 = tf32c(al[(it0 + tg + 8) * 133 + h * 33 + kb + tq + 4]);
            #pragma unroll
            for (int nt = 0; nt < 7; nt++) {
                uint b0 = tf32c(ve[(kb + tq) * 226 + h * 56 + nt * 8 + tg]);
                uint b1 = tf32c(ve[(kb + tq + 4) * 226 + h * 56 + nt * 8 + tg]);
                MMA_TF32(d2[nt], a0, a1, a2, a3, b0, b1);
            }
        }
        #pragma unroll
        for (int nt = 0; nt < 7; nt++) {
            int j = nt * 8 + 2 * tq;
            int i_lo = it0 + tg, i_hi = i_lo + 8;
            size_t g_lo = (size_t)(nb + i_lo) * 16 + c;
            size_t g_hi = (size_t)(nb + i_hi) * 16 + c;
            if (j < 32) {
                *(float2*)&out[g_lo * 128 + h * 32 + j] = make_float2(d2[nt][0], d2[nt][1]);
                *(float2*)&out[g_hi * 128 + h * 32 + j] = make_float2(d2[nt][2], d2[nt][3]);
            } else {
                *(float2*)&out[(size_t)NC_ITEMS * 128 + g_lo * 96 + h * 24 + j - 32] =
                    make_float2(d2[nt][0], d2[nt][1]);
                *(float2*)&out[(size_t)NC_ITEMS * 128 + g_hi * 96 + h * 24 + j - 32] =
                    make_float2(d2[nt][2], d2[nt][3]);
            }
        }
    }
}

// ============================================================
extern "C" void kernel_launch(void* const* d_in, const int* in_sizes, int n_in,
                              void* d_out, int out_size) {
    (void)in_sizes; (void)n_in; (void)out_size;
    const float* s       = (const float*)d_in[0];
    const float* v       = (const float*)d_in[1];
    const float* wp_wh   = (const float*)d_in[2];
    const float* wp_ws_w = (const float*)d_in[3];
    const float* wp_ws_b = (const float*)d_in[4];
    const float* q_wh    = (const float*)d_in[5];
    const float* q_ws_w  = (const float*)d_in[6];
    const float* q_ws_b  = (const float*)d_in[7];
    const float* q_wv    = (const float*)d_in[8];
    const float* q_wsv_w = (const float*)d_in[9];
    const float* q_wsv_b = (const float*)d_in[10];
    const float* k_wh    = (const float*)d_in[11];
    const float* k_ws_w  = (const float*)d_in[12];
    const float* k_ws_b  = (const float*)d_in[13];
    const float* k_wv    = (const float*)d_in[14];
    const float* k_wsv_w = (const float*)d_in[15];
    const float* k_wsv_b = (const float*)d_in[16];
    const float* vp_wh   = (const float*)d_in[17];
    const float* vp_ws_w = (const float*)d_in[18];
    const float* vp_ws_b = (const float*)d_in[19];
    const float* vp_wv   = (const float*)d_in[20];
    const float* vp_wsv_w= (const float*)d_in[21];
    const float* vp_wsv_b= (const float*)d_in[22];
    float* out = (float*)d_out;

    cudaFuncSetAttribute((const void*)ka_gvp,  cudaFuncAttributeMaxDynamicSharedMemorySize, KA_SMEMF * 4);
    cudaFuncSetAttribute((const void*)kb_attn, cudaFuncAttributeMaxDynamicSharedMemorySize, 26496 * 4);

    k0b<<<20, 256>>>(wp_ws_w);
    k0c<<<16, 256>>>(q_wsv_w);
    kz<<<1, 32>>>();
    ka_gvp<<<2048, 512, KA_SMEMF * 4>>>(s, v, q_wh, q_ws_w, q_ws_b, q_wv,
                                        q_wsv_b, wp_wh, wp_ws_b);   // 4th -> profiled
    k2a_stats<<<dim3(16, 16), 256>>>();
    k3_compress<<<dim3(NCHUNK, C_DIM), 224>>>(s, v);
    k4_reduce<<<512, 224>>>();
    k5_globals<<<128, 256>>>(k_wh, k_ws_w, k_ws_b, k_wv, k_wsv_w, k_wsv_b,
                             vp_wh, vp_ws_w, vp_ws_b, vp_wv, vp_wsv_w, vp_wsv_b);
    kb_attn<<<dim3(256, C_DIM), 256, 26496 * 4>>>(out);
}

// round 14
// speedup vs baseline: 1.2500x; 1.0487x over previous
#include <cuda_runtime.h>

#define N_NODES 8192
#define C_DIM   16
#define NC_ITEMS (N_NODES * C_DIM)
#define R_ANCH  32
#define XD      224
#define NCHUNK  64
#define ESCALE  0.15811388300841898f

typedef unsigned long long ull;
typedef unsigned int uint;

__device__ float g_logits[NC_ITEMS * R_ANCH];
__device__ float g_pm[C_DIM * 16 * R_ANCH];
__device__ float g_ps[C_DIM * 16 * R_ANCH];
__device__ float g_part[NCHUNK * C_DIM * R_ANCH * XD];
__device__ float g_gbuf[R_ANCH * C_DIM * XD];
__device__ float g_ke[C_DIM * R_ANCH * XD];
__device__ float g_ve[C_DIM * R_ANCH * XD];
__device__ float g_q[(size_t)NC_ITEMS * XD];
__device__ float g_wsvT[128 * 32];

__device__ __forceinline__ float sigf(float x) { return 1.0f / (1.0f + __expf(-x)); }
#define FMA2(d, a, b) asm("fma.rn.f32x2 %0, %1, %2, %0;" : "+l"(d) : "l"(a), "l"(b))
__device__ __forceinline__ ull packx2(float x) {
    ull o; unsigned r = __float_as_uint(x);
    asm("mov.b64 %0, {%1, %1};" : "=l"(o) : "r"(r));
    return o;
}
__device__ __forceinline__ float2 unpk(ull u) {
    float2 f;
    asm("mov.b64 {%0, %1}, %2;" : "=f"(f.x), "=f"(f.y) : "l"(u));
    return f;
}
__device__ __forceinline__ uint tf32c(float f) {
    uint u;
    asm("cvt.rna.tf32.f32 %0, %1;" : "=r"(u) : "f"(f));
    return u;
}
#define MMA_TF32(d, a0, a1, a2, a3, b0, b1) \
    asm volatile("mma.sync.aligned.m16n8k8.row.col.f32.tf32.tf32.f32 " \
        "{%0,%1,%2,%3}, {%4,%5,%6,%7}, {%8,%9}, {%0,%1,%2,%3};" \
        : "+f"(d[0]), "+f"(d[1]), "+f"(d[2]), "+f"(d[3]) \
        : "r"(a0), "r"(a1), "r"(a2), "r"(a3), "r"(b0), "r"(b1))

__global__ void kz(int p) { if (threadIdx.x == 0) g_pm[p] = 0.f; }
__global__ void k0c(const float* __restrict__ sv) {
    int i = blockIdx.x * 256 + threadIdx.x;
    if (i < 128 * 32) { int k = i >> 5, m = i & 31; g_wsvT[i] = sv[m * 128 + k]; }
}

// ---- ka smem offsets (floats) ----
#define OF_WQOM 0        // [128][164] tf32 [o][k]
#define OF_WP   20992    // [160? no: 32][164] fp32 [a][k]
#define OF_WSVT 26240    // [128][36] tf32 [k][m]
#define OF_WHQ  30848    // [32][34]
#define OF_WHP  31936    // [32][34]
#define OF_WVM  33024    // [32][36] tf32 [m][h]
#define OF_SBQ  34176
#define OF_SBP  34304
#define OF_SVB  34336
#define OF_XS   34368    // [160][68]: rows 0..127 x_s (later vstage), 128..159 vn_q
#define OF_VNP  45248    // [32][68] vn_p
#define OF_VHT  47424    // [32][193] vh transposed [h][(i*3+d)]
#define OF_GSB  53600    // [64][33]; vbuf overlay
#define KA_SMEMF 55712

// ============================================================
// KA: 64 items/block, 512 threads. All GEMMs on tensor cores:
// warps 0-7 s_out (1xTF32); warps 8-15 logits (3xTF32) + v_out (1xTF32);
// gate (1xTF32) on warps 0-3.
// ============================================================
__global__ void __launch_bounds__(512) ka_gvp(
    const float* __restrict__ s, const float* __restrict__ v,
    const float* __restrict__ q_wh, const float* __restrict__ q_ws_w,
    const float* __restrict__ q_ws_b, const float* __restrict__ q_wv,
    const float* __restrict__ q_wsv_b,
    const float* __restrict__ wp_wh, const float* __restrict__ wp_ws_w,
    const float* __restrict__ wp_ws_b)
{
    extern __shared__ float sm[];
    float* wqom = sm + OF_WQOM;
    float* wp   = sm + OF_WP;
    float* wsvt = sm + OF_WSVT;
    float* whq  = sm + OF_WHQ;
    float* whp  = sm + OF_WHP;
    float* wvm  = sm + OF_WVM;
    float* sbq  = sm + OF_SBQ;
    float* sbp  = sm + OF_SBP;
    float* svb  = sm + OF_SVB;
    float* xs   = sm + OF_XS;
    float* vnp  = sm + OF_VNP;
    float* vht  = sm + OF_VHT;
    float* gsb  = sm + OF_GSB;
    float* vbuf = sm + OF_GSB;   // overlay: vbuf in stage A only, gsb in gate phase

    int tid = threadIdx.x, warp = tid >> 5, lane = tid & 31;
    int base = blockIdx.x * 64;

    for (int i = tid; i < 128 * 160; i += 512) {
        int r = i / 160, c = i - r * 160;
        wqom[r * 164 + c] = __uint_as_float(tf32c(q_ws_w[i]));
    }
    for (int i = tid; i < 32 * 160; i += 512) {
        int r = i / 160, c = i - r * 160;
        wp[r * 164 + c] = wp_ws_w[i];
    }
    for (int i = tid; i < 4096; i += 512) {
        int k = i >> 5, m = i & 31;
        wsvt[k * 36 + m] = __uint_as_float(tf32c(g_wsvT[i]));
    }
    for (int i = tid; i < 1024; i += 512) {
        int r = i >> 5, cc = i & 31;
        whq[r * 34 + cc] = q_wh[i];
        whp[r * 34 + cc] = wp_wh[i];
        wvm[r * 36 + cc] = __uint_as_float(tf32c(q_wv[i]));   // [m][h]
    }
    if (tid < 128) sbq[tid] = q_ws_b[tid];
    if (tid < 32)  { sbp[tid] = wp_ws_b[tid]; svb[tid] = q_wsv_b[tid]; }
    __syncthreads();

    // ---- stage A: 16 warps x 4 items
    {
        float* vb = vbuf + warp * 104;
        for (int ii = 0; ii < 4; ii++) {
            int i = warp * 4 + ii;
            size_t git = (size_t)(base + i);
            const float* sp = s + git * 128;
            const float* vpp = v + git * 96;
            #pragma unroll
            for (int k = 0; k < 4; k++) xs[(lane + 32 * k) * 68 + i] = sp[lane + 32 * k];
            #pragma unroll
            for (int k = 0; k < 3; k++) {
                int pos = lane + 32 * k;
                float val = vpp[pos];
                int m = pos / 3, d = pos - m * 3;
                vb[d * 34 + m] = val;
            }
            __syncwarp();
            ull aq0 = 0, aq1 = 0, aq2 = 0, ap0 = 0, ap1 = 0, ap2 = 0;
            #pragma unroll
            for (int m2 = 0; m2 < 32; m2 += 2) {
                ull wqp = *(const ull*)&whq[lane * 34 + m2];
                ull wpp = *(const ull*)&whp[lane * 34 + m2];
                ull v0 = *(const ull*)&vb[m2];
                ull v1 = *(const ull*)&vb[34 + m2];
                ull v2 = *(const ull*)&vb[68 + m2];
                FMA2(aq0, v0, wqp); FMA2(aq1, v1, wqp); FMA2(aq2, v2, wqp);
                FMA2(ap0, v0, wpp); FMA2(ap1, v1, wpp); FMA2(ap2, v2, wpp);
            }
            float2 f;
            f = unpk(aq0); float a0 = f.x + f.y;
            f = unpk(aq1); float a1 = f.x + f.y;
            f = unpk(aq2); float a2 = f.x + f.y;
            f = unpk(ap0); float b0 = f.x + f.y;
            f = unpk(ap1); float b1 = f.x + f.y;
            f = unpk(ap2); float b2 = f.x + f.y;
            vht[lane * 193 + i * 3 + 0] = a0;
            vht[lane * 193 + i * 3 + 1] = a1;
            vht[lane * 193 + i * 3 + 2] = a2;
            xs[(128 + lane) * 68 + i] = sqrtf(fmaxf(a0 * a0 + a1 * a1 + a2 * a2, 1e-8f));
            vnp[lane * 68 + i]        = sqrtf(fmaxf(b0 * b0 + b1 * b1 + b2 * b2, 1e-8f));
            __syncwarp();
        }
    }
    __syncthreads();

    float sg[8][4];        // s_out sigmoids (warps 0-7)
    float dv[2][4][4];     // v_out fragments (warps 8-15; w8-11 use 2 tiles)
    int tg = lane >> 2, tq = lane & 3;

    if (warp < 8) {
        // ---- s_out 1xTF32: warp = 16i x 64o
        int itile = (warp & 3) * 16, n0base = (warp >> 2) * 64;
        float d[8][4] = {};
        #pragma unroll
        for (int kk = 0; kk < 20; kk++) {
            int kb = kk * 8;
            uint a0 = tf32c(xs[(kb + tq) * 68 + itile + tg]);
            uint a1 = tf32c(xs[(kb + tq) * 68 + itile + tg + 8]);
            uint a2 = tf32c(xs[(kb + tq + 4) * 68 + itile + tg]);
            uint a3 = tf32c(xs[(kb + tq + 4) * 68 + itile + tg + 8]);
            #pragma unroll
            for (int nt = 0; nt < 8; nt++) {
                const float* wb = wqom + (n0base + nt * 8 + tg) * 164 + kb + tq;
                uint b0 = __float_as_uint(wb[0]);
                uint b1 = __float_as_uint(wb[4]);
                MMA_TF32(d[nt], a0, a1, a2, a3, b0, b1);
            }
        }
        #pragma unroll
        for (int nt = 0; nt < 8; nt++) {
            int o = n0base + nt * 8 + 2 * tq;
            float bb0 = sbq[o], bb1 = sbq[o + 1];
            int gp0 = (o >> 5) * 56 + (o & 31);
            int i_lo = itile + tg, i_hi = i_lo + 8;
            float s00 = d[nt][0] + bb0, s01 = d[nt][1] + bb1;
            float s10 = d[nt][2] + bb0, s11 = d[nt][3] + bb1;
            float g00 = sigf(s00), g01 = sigf(s01), g10 = sigf(s10), g11 = sigf(s11);
            sg[nt][0] = g00; sg[nt][1] = g01; sg[nt][2] = g10; sg[nt][3] = g11;
            *(float2*)&g_q[(size_t)(base + i_lo) * 224 + gp0] = make_float2(s00 * g00, s01 * g01);
            *(float2*)&g_q[(size_t)(base + i_hi) * 224 + gp0] = make_float2(s10 * g10, s11 * g11);
        }
    } else {
        int w2 = warp - 8;
        // ---- logits 3xTF32: warp = 16i x 16a
        {
            int it0 = (w2 & 3) * 16, a0b = (w2 >> 2) * 16;
            float d[2][4] = {};
            #pragma unroll
            for (int kk = 0; kk < 20; kk++) {
                int kb = kk * 8;
                float x0f, x1f, x2f, x3f;
                if (kb < 128) {
                    x0f = xs[(kb + tq) * 68 + it0 + tg];
                    x1f = xs[(kb + tq) * 68 + it0 + tg + 8];
                    x2f = xs[(kb + tq + 4) * 68 + it0 + tg];
                    x3f = xs[(kb + tq + 4) * 68 + it0 + tg + 8];
                } else {
                    x0f = vnp[(kb - 128 + tq) * 68 + it0 + tg];
                    x1f = vnp[(kb - 128 + tq) * 68 + it0 + tg + 8];
                    x2f = vnp[(kb - 124 + tq) * 68 + it0 + tg];
                    x3f = vnp[(kb - 124 + tq) * 68 + it0 + tg + 8];
                }
                uint ah0 = tf32c(x0f), ah1 = tf32c(x1f), ah2 = tf32c(x2f), ah3 = tf32c(x3f);
                uint al0 = tf32c(x0f - __uint_as_float(ah0));
                uint al1 = tf32c(x1f - __uint_as_float(ah1));
                uint al2 = tf32c(x2f - __uint_as_float(ah2));
                uint al3 = tf32c(x3f - __uint_as_float(ah3));
                #pragma unroll
                for (int nt = 0; nt < 2; nt++) {
                    const float* wb = wp + (a0b + nt * 8 + tg) * 164 + kb + tq;
                    float w0f = wb[0], w1f = wb[4];
                    uint bh0 = tf32c(w0f), bh1 = tf32c(w1f);
                    uint bl0 = tf32c(w0f - __uint_as_float(bh0));
                    uint bl1 = tf32c(w1f - __uint_as_float(bh1));
                    MMA_TF32(d[nt], ah0, ah1, ah2, ah3, bh0, bh1);
                    MMA_TF32(d[nt], al0, al1, al2, al3, bh0, bh1);
                    MMA_TF32(d[nt], ah0, ah1, ah2, ah3, bl0, bl1);
                }
            }
            #pragma unroll
            for (int nt = 0; nt < 2; nt++) {
                int a = a0b + nt * 8 + 2 * tq;
                float b0 = sbp[a], b1 = sbp[a + 1];
                int i_lo = it0 + tg, i_hi = i_lo + 8;
                *(float2*)&g_logits[(size_t)(base + i_lo) * 32 + a] =
                    make_float2(d[nt][0] + b0, d[nt][1] + b1);
                *(float2*)&g_logits[(size_t)(base + i_hi) * 32 + a] =
                    make_float2(d[nt][2] + b0, d[nt][3] + b1);
            }
        }
        // ---- v_out 1xTF32: 12 row-tiles over warps 8-15
        {
            int ntile = (w2 < 4) ? 2 : 1;
            #pragma unroll
            for (int t = 0; t < 2; t++) {
                if (t >= ntile) break;
                int rt = (w2 < 4) ? (w2 * 2 + t) : (8 + (w2 - 4));
                float* dd = dv[t][0];
                #pragma unroll
                for (int nt = 0; nt < 4; nt++)
                    #pragma unroll
                    for (int u = 0; u < 4; u++) dv[t][nt][u] = 0.f;
                #pragma unroll
                for (int kk = 0; kk < 4; kk++) {
                    int kb = kk * 8;
                    uint a0 = tf32c(vht[(kb + tq) * 193 + rt * 16 + tg]);
                    uint a1 = tf32c(vht[(kb + tq) * 193 + rt * 16 + tg + 8]);
                    uint a2 = tf32c(vht[(kb + tq + 4) * 193 + rt * 16 + tg]);
                    uint a3 = tf32c(vht[(kb + tq + 4) * 193 + rt * 16 + tg + 8]);
                    #pragma unroll
                    for (int nt = 0; nt < 4; nt++) {
                        uint b0 = __float_as_uint(wvm[(nt * 8 + tg) * 36 + kb + tq]);
                        uint b1 = __float_as_uint(wvm[(nt * 8 + tg) * 36 + kb + tq + 4]);
                        MMA_TF32(dv[t][nt], a0, a1, a2, a3, b0, b1);
                    }
                }
                (void)dd;
            }
        }
    }
    __syncthreads();   // all xs/vnp/vht readers done

    if (warp < 8) {
        // sigmoids -> xs cols 0..127
        int itile = (warp & 3) * 16, n0base = (warp >> 2) * 64;
        #pragma unroll
        for (int nt = 0; nt < 8; nt++) {
            int o = n0base + nt * 8 + 2 * tq;
            int i_lo = itile + tg, i_hi = i_lo + 8;
            xs[o * 68 + i_lo]       = sg[nt][0];
            xs[(o + 1) * 68 + i_lo] = sg[nt][1];
            xs[o * 68 + i_hi]       = sg[nt][2];
            xs[(o + 1) * 68 + i_hi] = sg[nt][3];
        }
    }
    __syncthreads();   // sig visible

    if (warp < 4) {
        // ---- gate 1xTF32: warp = 16i x 32m
        int itile = warp * 16;
        float d[4][4] = {};
        #pragma unroll
        for (int kk = 0; kk < 16; kk++) {
            int kb = kk * 8;
            uint a0 = tf32c(xs[(kb + tq) * 68 + itile + tg]);
            uint a1 = tf32c(xs[(kb + tq) * 68 + itile + tg + 8]);
            uint a2 = tf32c(xs[(kb + tq + 4) * 68 + itile + tg]);
            uint a3 = tf32c(xs[(kb + tq + 4) * 68 + itile + tg + 8]);
            #pragma unroll
            for (int nt = 0; nt < 4; nt++) {
                uint b0 = __float_as_uint(wsvt[(kb + tq) * 36 + nt * 8 + tg]);
                uint b1 = __float_as_uint(wsvt[(kb + tq + 4) * 36 + nt * 8 + tg]);
                MMA_TF32(d[nt], a0, a1, a2, a3, b0, b1);
            }
        }
        #pragma unroll
        for (int nt = 0; nt < 4; nt++) {
            int m = nt * 8 + 2 * tq;
            float b0 = svb[m], b1 = svb[m + 1];
            int i_lo = itile + tg, i_hi = i_lo + 8;
            gsb[i_lo * 33 + m]     = sigf(d[nt][0] + b0);
            gsb[i_lo * 33 + m + 1] = sigf(d[nt][1] + b1);
            gsb[i_hi * 33 + m]     = sigf(d[nt][2] + b0);
            gsb[i_hi * 33 + m + 1] = sigf(d[nt][3] + b1);
        }
    }
    __syncthreads();   // gsb visible; xs sig reads complete

    if (warp >= 8) {
        int w2 = warp - 8;
        float* vstage = xs;   // reuse xs as [64][97]
        int ntile = (w2 < 4) ? 2 : 1;
        #pragma unroll
        for (int t = 0; t < 2; t++) {
            if (t >= ntile) break;
            int rt = (w2 < 4) ? (w2 * 2 + t) : (8 + (w2 - 4));
            #pragma unroll
            for (int nt = 0; nt < 4; nt++) {
                int m = nt * 8 + 2 * tq;
                #pragma unroll
                for (int rr = 0; rr < 2; rr++) {
                    int row = rt * 16 + tg + rr * 8;
                    int i = row / 3, dd2 = row - i * 3;
                    float gv0 = gsb[i * 33 + m], gv1 = gsb[i * 33 + m + 1];
                    vstage[i * 97 + m * 3 + dd2]       = dv[t][nt][rr * 2]     * gv0;
                    vstage[i * 97 + (m + 1) * 3 + dd2] = dv[t][nt][rr * 2 + 1] * gv1;
                }
            }
        }
        asm volatile("bar.sync 1, 256;" ::: "memory");
        // coalesced v stores: warp handles 8 items
        for (int ii = 0; ii < 8; ii++) {
            int item = w2 * 8 + ii;
            size_t gb2 = (size_t)(base + item) * 224;
            #pragma unroll
            for (int q = 0; q < 3; q++) {
                int l = lane + 32 * q;
                int m = l / 3, d = l - m * 3;
                int gpos = (m >> 3) * 56 + 32 + (m & 7) * 3 + d;
                g_q[gb2 + gpos] = vstage[item * 97 + l];
            }
        }
    }
}

// ---- K2a ----
__global__ void __launch_bounds__(256) k2a_stats() {
    __shared__ float redm[8 * 33], reds[8 * 33];
    int seg = blockIdx.x, c = blockIdx.y;
    int t = threadIdx.x, a = t & 31, part = t >> 5;
    float m = -3.4e38f, sum = 0.f;
    int nb = seg * 512 + part * 64;
    for (int i = 0; i < 64; i++) {
        float val = g_logits[((size_t)(nb + i) * C_DIM + c) * 32 + a];
        float nm = fmaxf(m, val);
        sum = sum * __expf(m - nm) + __expf(val - nm);
        m = nm;
    }
    redm[part * 33 + a] = m; reds[part * 33 + a] = sum;
    __syncthreads();
    if (t < 32) {
        float mm = redm[t], ss = reds[t];
        #pragma unroll
        for (int p = 1; p < 8; p++) {
            float m2 = redm[p * 33 + t], s2 = reds[p * 33 + t];
            float nm = fmaxf(mm, m2);
            ss = ss * __expf(mm - nm) + s2 * __expf(m2 - nm);
            mm = nm;
        }
        g_pm[(c * 16 + seg) * 32 + t] = mm;
        g_ps[(c * 16 + seg) * 32 + t] = ss;
    }
}

// ---- K3 ----
__global__ void __launch_bounds__(224) k3_compress(const float* __restrict__ s,
                                                   const float* __restrict__ v) {
    __shared__ float xt[32 * 226];
    __shared__ float wt[32 * 33];
    __shared__ float mloc[32], iloc[32];
    int t = threadIdx.x;
    int chunk = blockIdx.x, c = blockIdx.y;
    if (t < 32) {
        float m = -3.4e38f;
        #pragma unroll
        for (int sg2 = 0; sg2 < 16; sg2++) m = fmaxf(m, g_pm[(c * 16 + sg2) * 32 + t]);
        float sum = 0.f;
        #pragma unroll
        for (int sg2 = 0; sg2 < 16; sg2++)
            sum += g_ps[(c * 16 + sg2) * 32 + t] * __expf(g_pm[(c * 16 + sg2) * 32 + t] - m);
        mloc[t] = m; iloc[t] = 1.0f / sum;
    }
    int a0 = (t & 7) * 4, j0 = (t >> 3) * 8;
    ull acc[4][4] = {};
    for (int sub = 0; sub < 4; sub++) {
        __syncthreads();
        #pragma unroll 4
        for (int n = 0; n < 32; n++) {
            int item = (chunk * 128 + sub * 32 + n) * C_DIM + c;
            xt[n * 226 + t] = (t < 128) ? s[(size_t)item * 128 + t]
                                        : v[(size_t)item * 96 + (t - 128)];
        }
        for (int idx = t; idx < 1024; idx += 224) {
            int n = idx >> 5, a = idx & 31;
            int item = (chunk * 128 + sub * 32 + n) * C_DIM + c;
            wt[n * 33 + a] = __expf(g_logits[(size_t)item * 32 + a] - mloc[a]) * iloc[a];
        }
        __syncthreads();
        #pragma unroll 4
        for (int n = 0; n < 32; n++) {
            ull wpk[4];
            #pragma unroll
            for (int u = 0; u < 4; u++) wpk[u] = packx2(wt[n * 33 + a0 + u]);
            const ull* x2 = (const ull*)(xt + n * 226 + j0);
            #pragma unroll
            for (int vv = 0; vv < 4; vv++) {
                ull xp = x2[vv];
                FMA2(acc[0][vv], wpk[0], xp);
                FMA2(acc[1][vv], wpk[1], xp);
                FMA2(acc[2][vv], wpk[2], xp);
                FMA2(acc[3][vv], wpk[3], xp);
            }
        }
    }
    #pragma unroll
    for (int u = 0; u < 4; u++) {
        size_t basep = ((size_t)(chunk * C_DIM + c) * 32 + a0 + u) * 224 + j0;
        #pragma unroll
        for (int vv = 0; vv < 4; vv++) {
            float2 fr = unpk(acc[u][vv]);
            *(float2*)&g_part[basep + 2 * vv] = fr;
        }
    }
}

// ---- K4 ----
__global__ void k4_reduce() {
    int bx = blockIdx.x; int c = bx >> 5, a = bx & 31; int t = threadIdx.x;
    float sum = 0.f;
    for (int ch = 0; ch < NCHUNK; ++ch)
        sum += g_part[((size_t)(ch * C_DIM + c) * 32 + a) * 224 + t];
    g_gbuf[(a * C_DIM + c) * 224 + t] = sum;
}

// ---- K5 ----
__global__ void k5_globals(
    const float* __restrict__ k_wh, const float* __restrict__ k_ws_w, const float* __restrict__ k_ws_b,
    const float* __restrict__ k_wv, const float* __restrict__ k_wsv_w, const float* __restrict__ k_wsv_b,
    const float* __restrict__ p_wh, const float* __restrict__ p_ws_w, const float* __restrict__ p_ws_b,
    const float* __restrict__ p_wv, const float* __restrict__ p_wsv_w, const float* __restrict__ p_wsv_b) {
    __shared__ float wx[8][608];
    int tid = threadIdx.x, warp = tid >> 5, lane = tid & 31;
    int w = blockIdx.x * 8 + warp;
    int which = w >> 9, item = w & 511;
    const float* wh   = which ? p_wh    : k_wh;
    const float* wsw  = which ? p_ws_w  : k_ws_w;
    const float* wsb  = which ? p_ws_b  : k_ws_b;
    const float* wv   = which ? p_wv    : k_wv;
    const float* wsvw = which ? p_wsv_w : k_wsv_w;
    const float* wsvb = which ? p_wsv_b : k_wsv_b;
    float* x = wx[warp]; float* vhsl = x + 224; float* vns = x + 320; float* sig = x + 480;
    const float* gp = &g_gbuf[item * 224];
    #pragma unroll
    for (int k = 0; k < 7; k++) x[lane + 32 * k] = gp[lane + 32 * k];
    __syncwarp();
    float a0 = 0.f, a1 = 0.f, a2 = 0.f;
    #pragma unroll
    for (int i = 0; i < 32; i++) {
        float ww = __ldg(&wh[lane * 32 + i]);
        a0 = fmaf(x[128 + i * 3 + 0], ww, a0);
        a1 = fmaf(x[128 + i * 3 + 1], ww, a1);
        a2 = fmaf(x[128 + i * 3 + 2], ww, a2);
    }
    vhsl[lane] = a0; vhsl[32 + lane] = a1; vhsl[64 + lane] = a2;
    vns[lane] = sqrtf(fmaxf(a0 * a0 + a1 * a1 + a2 * a2, 1e-8f));
    __syncwarp();
    float so[4];
    #pragma unroll
    for (int k = 0; k < 4; k++) {
        int o = lane + 32 * k;
        float acc = __ldg(&wsb[o]);
        const float* wr = &wsw[o * 160];
        #pragma unroll
        for (int j = 0; j < 128; j++) acc = fmaf(x[j], __ldg(&wr[j]), acc);
        #pragma unroll
        for (int j = 0; j < 32; j++) acc = fmaf(vns[j], __ldg(&wr[128 + j]), acc);
        so[k] = acc;
        sig[o] = sigf(acc);
    }
    __syncwarp();
    float g = __ldg(&wsvb[lane]);
    #pragma unroll
    for (int j = 0; j < 128; j++) g = fmaf(sig[j], __ldg(&wsvw[lane * 128 + j]), g);
    float gs = sigf(g);
    float* outp = which ? g_ve : g_ke;
    int a = item >> 4, cc = item & 15;
    size_t ob = ((size_t)cc * 32 + a) * 224;
    int h = lane >> 3;
    int vpos = h * 56 + 32 + (lane & 7) * 3;
    #pragma unroll
    for (int d = 0; d < 3; d++) {
        float vo = 0.f;
        #pragma unroll
        for (int hh = 0; hh < 32; hh++) vo = fmaf(vhsl[d * 32 + hh], __ldg(&wv[lane * 32 + hh]), vo);
        outp[ob + vpos + d] = vo * gs;
    }
    #pragma unroll
    for (int k = 0; k < 4; k++) { int o = lane + 32 * k; outp[ob + k * 56 + lane] = so[k] * sig[o]; }
}

// ============================================================
// KB: attention via tf32 mma. 32 items x 1 channel, 256 threads.
// ============================================================
__global__ void __launch_bounds__(256) kb_attn(float* __restrict__ out) {
    extern __shared__ float sm[];
    float* qe  = sm;            // [224][33] tf32 bits
    float* keT = sm + 7392;     // [224][34] tf32 bits
    float* ve  = sm + 15008;    // [32][226] fp32
    float* al  = sm + 22240;    // [32][133] fp32
    int tid = threadIdx.x;
    int c = blockIdx.y;
    int nb = blockIdx.x * 32;

    for (int idx = tid; idx < 32 * 224; idx += 256) {
        int i = idx / 224, pos = idx - i * 224;
        size_t git = (size_t)(nb + i) * 16 + c;
        qe[pos * 33 + i] = __uint_as_float(tf32c(g_q[git * 224 + pos]));
    }
    for (int idx = tid; idx < 32 * 224; idx += 256) {
        int r = idx / 224, pos = idx - r * 224;
        size_t gb = ((size_t)c * 32 + r) * 224 + pos;
        keT[pos * 34 + r] = __uint_as_float(tf32c(g_ke[gb]));
        ve[r * 226 + pos] = g_ve[gb];
    }
    __syncthreads();

    int warp = tid >> 5, lane = tid & 31;
    int h = warp >> 1, mt = warp & 1;
    int it0 = mt * 16;
    int tg = lane >> 2, tq = lane & 3;

    {
        float d[4][4] = {};
        #pragma unroll
        for (int kk = 0; kk < 7; kk++) {
            int kbase = h * 56 + kk * 8;
            uint a0 = __float_as_uint(qe[(kbase + tq) * 33 + it0 + tg]);
            uint a1 = __float_as_uint(qe[(kbase + tq) * 33 + it0 + tg + 8]);
            uint a2 = __float_as_uint(qe[(kbase + tq + 4) * 33 + it0 + tg]);
            uint a3 = __float_as_uint(qe[(kbase + tq + 4) * 33 + it0 + tg + 8]);
            #pragma unroll
            for (int nt = 0; nt < 4; nt++) {
                uint b0 = __float_as_uint(keT[(kbase + tq) * 34 + nt * 8 + tg]);
                uint b1 = __float_as_uint(keT[(kbase + tq + 4) * 34 + nt * 8 + tg]);
                MMA_TF32(d[nt], a0, a1, a2, a3, b0, b1);
            }
        }
        #pragma unroll
        for (int nt = 0; nt < 4; nt++) {
            int a = nt * 8 + 2 * tq;
            int i_lo = it0 + tg, i_hi = i_lo + 8;
            al[i_lo * 133 + h * 33 + a]     = d[nt][0] * ESCALE;
            al[i_lo * 133 + h * 33 + a + 1] = d[nt][1] * ESCALE;
            al[i_hi * 133 + h * 33 + a]     = d[nt][2] * ESCALE;
            al[i_hi * 133 + h * 33 + a + 1] = d[nt][3] * ESCALE;
        }
    }
    __syncthreads();

    if (tid < 128) {
        int i = tid >> 2, h2 = tid & 3;
        float* row = &al[i * 133 + h2 * 33];
        float ev[32], mx = -3.4e38f;
        #pragma unroll
        for (int k = 0; k < 32; k++) { ev[k] = row[k]; mx = fmaxf(mx, ev[k]); }
        float sum = 0.f;
        #pragma unroll
        for (int k = 0; k < 32; k++) { ev[k] = __expf(ev[k] - mx); sum += ev[k]; }
        float inv = 1.0f / sum;
        #pragma unroll
        for (int k = 0; k < 32; k++) row[k] = ev[k] * inv;
    }
    __syncthreads();

    {
        float d2[7][4] = {};
        #pragma unroll
        for (int kk = 0; kk < 4; kk++) {
            int kb = kk * 8;
            uint a0 = tf32c(al[(it0 + tg) * 133 + h * 33 + kb + tq]);
            uint a1 = tf32c(al[(it0 + tg + 8) * 133 + h * 33 + kb + tq]);
            uint a2 = tf32c(al[(it0 + tg) * 133 + h * 33 + kb + tq + 4]);
            uint a3 = tf32c(al[(it0 + tg + 8) * 133 + h * 33 + kb + tq + 4]);
            #pragma unroll
            for (int nt = 0; nt < 7; nt++) {
                uint b0 = tf32c(ve[(kb + tq) * 226 + h * 56 + nt * 8 + tg]);
                uint b1 = tf32c(ve[(kb + tq + 4) * 226 + h * 56 + nt * 8 + tg]);
                MMA_TF32(d2[nt], a0, a1, a2, a3, b0, b1);
            }
        }
        #pragma unroll
        for (int nt = 0; nt < 7; nt++) {
            int j = nt * 8 + 2 * tq;
            int i_lo = it0 + tg, i_hi = i_lo + 8;
            size_t g_lo = (size_t)(nb + i_lo) * 16 + c;
            size_t g_hi = (size_t)(nb + i_hi) * 16 + c;
            if (j < 32) {
                *(float2*)&out[g_lo * 128 + h * 32 + j] = make_float2(d2[nt][0], d2[nt][1]);
                *(float2*)&out[g_hi * 128 + h * 32 + j] = make_float2(d2[nt][2], d2[nt][3]);
            } else {
                *(float2*)&out[(size_t)NC_ITEMS * 128 + g_lo * 96 + h * 24 + j - 32] =
                    make_float2(d2[nt][0], d2[nt][1]);
                *(float2*)&out[(size_t)NC_ITEMS * 128 + g_hi * 96 + h * 24 + j - 32] =
                    make_float2(d2[nt][2], d2[nt][3]);
            }
        }
    }
}

// ============================================================
extern "C" void kernel_launch(void* const* d_in, const int* in_sizes, int n_in,
                              void* d_out, int out_size) {
    (void)in_sizes; (void)n_in; (void)out_size;
    const float* s       = (const float*)d_in[0];
    const float* v       = (const float*)d_in[1];
    const float* wp_wh   = (const float*)d_in[2];
    const float* wp_ws_w = (const float*)d_in[3];
    const float* wp_ws_b = (const float*)d_in[4];
    const float* q_wh    = (const float*)d_in[5];
    const float* q_ws_w  = (const float*)d_in[6];
    const float* q_ws_b  = (const float*)d_in[7];
    const float* q_wv    = (const float*)d_in[8];
    const float* q_wsv_w = (const float*)d_in[9];
    const float* q_wsv_b = (const float*)d_in[10];
    const float* k_wh    = (const float*)d_in[11];
    const float* k_ws_w  = (const float*)d_in[12];
    const float* k_ws_b  = (const float*)d_in[13];
    const float* k_wv    = (const float*)d_in[14];
    const float* k_wsv_w = (const float*)d_in[15];
    const float* k_wsv_b = (const float*)d_in[16];
    const float* vp_wh   = (const float*)d_in[17];
    const float* vp_ws_w = (const float*)d_in[18];
    const float* vp_ws_b = (const float*)d_in[19];
    const float* vp_wv   = (const float*)d_in[20];
    const float* vp_wsv_w= (const float*)d_in[21];
    const float* vp_wsv_b= (const float*)d_in[22];
    float* out = (float*)d_out;

    cudaFuncSetAttribute((const void*)ka_gvp,  cudaFuncAttributeMaxDynamicSharedMemorySize, KA_SMEMF * 4);
    cudaFuncSetAttribute((const void*)kb_attn, cudaFuncAttributeMaxDynamicSharedMemorySize, 26496 * 4);

    k0c<<<16, 256>>>(q_wsv_w);
    kz<<<1, 32>>>(0);
    kz<<<1, 32>>>(1);
    ka_gvp<<<2048, 512, KA_SMEMF * 4>>>(s, v, q_wh, q_ws_w, q_ws_b, q_wv,
                                        q_wsv_b, wp_wh, wp_ws_w, wp_ws_b);  // 4th -> profiled
    k2a_stats<<<dim3(16, 16), 256>>>();
    k3_compress<<<dim3(NCHUNK, C_DIM), 224>>>(s, v);
    k4_reduce<<<512, 224>>>();
    k5_globals<<<128, 256>>>(k_wh, k_ws_w, k_ws_b, k_wv, k_wsv_w, k_wsv_b,
                             vp_wh, vp_ws_w, vp_ws_b, vp_wv, vp_wsv_w, vp_wsv_b);
    kb_attn<<<dim3(256, C_DIM), 256, 26496 * 4>>>(out);
}

// round 15
// speedup vs baseline: 1.3997x; 1.1198x over previous
#include <cuda_runtime.h>

#define N_NODES 8192
#define C_DIM   16
#define NC_ITEMS (N_NODES * C_DIM)
#define R_ANCH  32
#define XD      224
#define NCHUNK  64
#define ESCALE  0.15811388300841898f

typedef unsigned long long ull;
typedef unsigned int uint;

__device__ float g_logits[NC_ITEMS * R_ANCH];
__device__ float g_pm[C_DIM * 16 * R_ANCH];
__device__ float g_ps[C_DIM * 16 * R_ANCH];
__device__ float g_part[NCHUNK * C_DIM * R_ANCH * XD];
__device__ float g_gbuf[R_ANCH * C_DIM * XD];
__device__ float g_ke[C_DIM * R_ANCH * XD];
__device__ float g_ve[C_DIM * R_ANCH * XD];
__device__ float g_q[(size_t)NC_ITEMS * XD];
__device__ float g_wsvT[128 * 32];

__device__ __forceinline__ float sigf(float x) { return 1.0f / (1.0f + __expf(-x)); }
#define FMA2(d, a, b) asm("fma.rn.f32x2 %0, %1, %2, %0;" : "+l"(d) : "l"(a), "l"(b))
__device__ __forceinline__ ull packx2(float x) {
    ull o; unsigned r = __float_as_uint(x);
    asm("mov.b64 %0, {%1, %1};" : "=l"(o) : "r"(r));
    return o;
}
__device__ __forceinline__ float2 unpk(ull u) {
    float2 f;
    asm("mov.b64 {%0, %1}, %2;" : "=f"(f.x), "=f"(f.y) : "l"(u));
    return f;
}
__device__ __forceinline__ uint tf32c(float f) {
    uint u;
    asm("cvt.rna.tf32.f32 %0, %1;" : "=r"(u) : "f"(f));
    return u;
}
#define MMA_TF32(d, a0, a1, a2, a3, b0, b1) \
    asm volatile("mma.sync.aligned.m16n8k8.row.col.f32.tf32.tf32.f32 " \
        "{%0,%1,%2,%3}, {%4,%5,%6,%7}, {%8,%9}, {%0,%1,%2,%3};" \
        : "+f"(d[0]), "+f"(d[1]), "+f"(d[2]), "+f"(d[3]) \
        : "r"(a0), "r"(a1), "r"(a2), "r"(a3), "r"(b0), "r"(b1))

__global__ void kz(int p) { if (threadIdx.x == 0) g_pm[p] = 0.f; }
__global__ void k0c(const float* __restrict__ sv) {
    int i = blockIdx.x * 256 + threadIdx.x;
    if (i < 128 * 32) { int k = i >> 5, m = i & 31; g_wsvT[i] = sv[m * 128 + k]; }
}

// ---- ka smem offsets (floats) ----
#define OF_WQOM 0        // [128][164] tf32 [o][k]
#define OF_WP   20992    // [32][164] fp32 [a][k]
#define OF_WSVT 26240    // [128][36] tf32 [k][m]
#define OF_WHQ  30848    // [32][34]
#define OF_WHP  31936    // [32][34]
#define OF_WVM  33024    // [32][36] tf32 [m][h]
#define OF_SBQ  34176
#define OF_SBP  34304
#define OF_SVB  34336
#define OF_XS   34368    // [160][68]
#define OF_VNP  45248    // [32][68]
#define OF_VHT  47424    // [32][193]
#define OF_GSB  53600    // [64][33]; vbuf overlay
#define KA_SMEMF 55712

// ============================================================
// KA: PERSISTENT, 148 blocks x 512 threads; weights loaded once,
// loop over 64-item tiles. All GEMMs on tensor cores.
// ============================================================
__global__ void __launch_bounds__(512) ka_gvp(
    const float* __restrict__ s, const float* __restrict__ v,
    const float* __restrict__ q_wh, const float* __restrict__ q_ws_w,
    const float* __restrict__ q_ws_b, const float* __restrict__ q_wv,
    const float* __restrict__ q_wsv_b,
    const float* __restrict__ wp_wh, const float* __restrict__ wp_ws_w,
    const float* __restrict__ wp_ws_b)
{
    extern __shared__ float sm[];
    float* wqom = sm + OF_WQOM;
    float* wp   = sm + OF_WP;
    float* wsvt = sm + OF_WSVT;
    float* whq  = sm + OF_WHQ;
    float* whp  = sm + OF_WHP;
    float* wvm  = sm + OF_WVM;
    float* sbq  = sm + OF_SBQ;
    float* sbp  = sm + OF_SBP;
    float* svb  = sm + OF_SVB;
    float* xs   = sm + OF_XS;
    float* vnp  = sm + OF_VNP;
    float* vht  = sm + OF_VHT;
    float* gsb  = sm + OF_GSB;
    float* vbuf = sm + OF_GSB;   // overlay

    int tid = threadIdx.x, warp = tid >> 5, lane = tid & 31;
    int tg = lane >> 2, tq = lane & 3;

    // ---- weights: load + convert ONCE ----
    for (int i = tid; i < 128 * 160; i += 512) {
        int r = i / 160, c = i - r * 160;
        wqom[r * 164 + c] = __uint_as_float(tf32c(q_ws_w[i]));
    }
    for (int i = tid; i < 32 * 160; i += 512) {
        int r = i / 160, c = i - r * 160;
        wp[r * 164 + c] = wp_ws_w[i];
    }
    for (int i = tid; i < 4096; i += 512) {
        int k = i >> 5, m = i & 31;
        wsvt[k * 36 + m] = __uint_as_float(tf32c(g_wsvT[i]));
    }
    for (int i = tid; i < 1024; i += 512) {
        int r = i >> 5, cc = i & 31;
        whq[r * 34 + cc] = q_wh[i];
        whp[r * 34 + cc] = wp_wh[i];
        wvm[r * 36 + cc] = __uint_as_float(tf32c(q_wv[i]));
    }
    if (tid < 128) sbq[tid] = q_ws_b[tid];
    if (tid < 32)  { sbp[tid] = wp_ws_b[tid]; svb[tid] = q_wsv_b[tid]; }

    for (int tile = blockIdx.x; tile < 2048; tile += 148) {
        int base = tile * 64;
        __syncthreads();   // weights ready / previous tile's xs readers done

        // ---- stage A: 16 warps x 4 items
        {
            float* vb = vbuf + warp * 104;
            for (int ii = 0; ii < 4; ii++) {
                int i = warp * 4 + ii;
                size_t git = (size_t)(base + i);
                const float* sp = s + git * 128;
                const float* vpp = v + git * 96;
                #pragma unroll
                for (int k = 0; k < 4; k++) xs[(lane + 32 * k) * 68 + i] = sp[lane + 32 * k];
                #pragma unroll
                for (int k = 0; k < 3; k++) {
                    int pos = lane + 32 * k;
                    float val = vpp[pos];
                    int m = pos / 3, d = pos - m * 3;
                    vb[d * 34 + m] = val;
                }
                __syncwarp();
                ull aq0 = 0, aq1 = 0, aq2 = 0, ap0 = 0, ap1 = 0, ap2 = 0;
                #pragma unroll
                for (int m2 = 0; m2 < 32; m2 += 2) {
                    ull wqp = *(const ull*)&whq[lane * 34 + m2];
                    ull wpp = *(const ull*)&whp[lane * 34 + m2];
                    ull v0 = *(const ull*)&vb[m2];
                    ull v1 = *(const ull*)&vb[34 + m2];
                    ull v2 = *(const ull*)&vb[68 + m2];
                    FMA2(aq0, v0, wqp); FMA2(aq1, v1, wqp); FMA2(aq2, v2, wqp);
                    FMA2(ap0, v0, wpp); FMA2(ap1, v1, wpp); FMA2(ap2, v2, wpp);
                }
                float2 f;
                f = unpk(aq0); float a0 = f.x + f.y;
                f = unpk(aq1); float a1 = f.x + f.y;
                f = unpk(aq2); float a2 = f.x + f.y;
                f = unpk(ap0); float b0 = f.x + f.y;
                f = unpk(ap1); float b1 = f.x + f.y;
                f = unpk(ap2); float b2 = f.x + f.y;
                vht[lane * 193 + i * 3 + 0] = a0;
                vht[lane * 193 + i * 3 + 1] = a1;
                vht[lane * 193 + i * 3 + 2] = a2;
                xs[(128 + lane) * 68 + i] = sqrtf(fmaxf(a0 * a0 + a1 * a1 + a2 * a2, 1e-8f));
                vnp[lane * 68 + i]        = sqrtf(fmaxf(b0 * b0 + b1 * b1 + b2 * b2, 1e-8f));
                __syncwarp();
            }
        }
        __syncthreads();

        float sg[8][4];
        float dv[2][4][4];

        if (warp < 8) {
            // ---- s_out 1xTF32: warp = 16i x 64o
            int itile = (warp & 3) * 16, n0base = (warp >> 2) * 64;
            float d[8][4] = {};
            #pragma unroll
            for (int kk = 0; kk < 20; kk++) {
                int kb = kk * 8;
                uint a0 = tf32c(xs[(kb + tq) * 68 + itile + tg]);
                uint a1 = tf32c(xs[(kb + tq) * 68 + itile + tg + 8]);
                uint a2 = tf32c(xs[(kb + tq + 4) * 68 + itile + tg]);
                uint a3 = tf32c(xs[(kb + tq + 4) * 68 + itile + tg + 8]);
                #pragma unroll
                for (int nt = 0; nt < 8; nt++) {
                    const float* wb = wqom + (n0base + nt * 8 + tg) * 164 + kb + tq;
                    uint b0 = __float_as_uint(wb[0]);
                    uint b1 = __float_as_uint(wb[4]);
                    MMA_TF32(d[nt], a0, a1, a2, a3, b0, b1);
                }
            }
            #pragma unroll
            for (int nt = 0; nt < 8; nt++) {
                int o = n0base + nt * 8 + 2 * tq;
                float bb0 = sbq[o], bb1 = sbq[o + 1];
                int gp0 = (o >> 5) * 56 + (o & 31);
                int i_lo = itile + tg, i_hi = i_lo + 8;
                float s00 = d[nt][0] + bb0, s01 = d[nt][1] + bb1;
                float s10 = d[nt][2] + bb0, s11 = d[nt][3] + bb1;
                float g00 = sigf(s00), g01 = sigf(s01), g10 = sigf(s10), g11 = sigf(s11);
                sg[nt][0] = g00; sg[nt][1] = g01; sg[nt][2] = g10; sg[nt][3] = g11;
                *(float2*)&g_q[(size_t)(base + i_lo) * 224 + gp0] = make_float2(s00 * g00, s01 * g01);
                *(float2*)&g_q[(size_t)(base + i_hi) * 224 + gp0] = make_float2(s10 * g10, s11 * g11);
            }
        } else {
            int w2 = warp - 8;
            // ---- logits 3xTF32: warp = 16i x 16a
            {
                int it0 = (w2 & 3) * 16, a0b = (w2 >> 2) * 16;
                float d[2][4] = {};
                #pragma unroll
                for (int kk = 0; kk < 20; kk++) {
                    int kb = kk * 8;
                    float x0f, x1f, x2f, x3f;
                    if (kb < 128) {
                        x0f = xs[(kb + tq) * 68 + it0 + tg];
                        x1f = xs[(kb + tq) * 68 + it0 + tg + 8];
                        x2f = xs[(kb + tq + 4) * 68 + it0 + tg];
                        x3f = xs[(kb + tq + 4) * 68 + it0 + tg + 8];
                    } else {
                        x0f = vnp[(kb - 128 + tq) * 68 + it0 + tg];
                        x1f = vnp[(kb - 128 + tq) * 68 + it0 + tg + 8];
                        x2f = vnp[(kb - 124 + tq) * 68 + it0 + tg];
                        x3f = vnp[(kb - 124 + tq) * 68 + it0 + tg + 8];
                    }
                    uint ah0 = tf32c(x0f), ah1 = tf32c(x1f), ah2 = tf32c(x2f), ah3 = tf32c(x3f);
                    uint al0 = tf32c(x0f - __uint_as_float(ah0));
                    uint al1 = tf32c(x1f - __uint_as_float(ah1));
                    uint al2 = tf32c(x2f - __uint_as_float(ah2));
                    uint al3 = tf32c(x3f - __uint_as_float(ah3));
                    #pragma unroll
                    for (int nt = 0; nt < 2; nt++) {
                        const float* wb = wp + (a0b + nt * 8 + tg) * 164 + kb + tq;
                        float w0f = wb[0], w1f = wb[4];
                        uint bh0 = tf32c(w0f), bh1 = tf32c(w1f);
                        uint bl0 = tf32c(w0f - __uint_as_float(bh0));
                        uint bl1 = tf32c(w1f - __uint_as_float(bh1));
                        MMA_TF32(d[nt], ah0, ah1, ah2, ah3, bh0, bh1);
                        MMA_TF32(d[nt], al0, al1, al2, al3, bh0, bh1);
                        MMA_TF32(d[nt], ah0, ah1, ah2, ah3, bl0, bl1);
                    }
                }
                #pragma unroll
                for (int nt = 0; nt < 2; nt++) {
                    int a = a0b + nt * 8 + 2 * tq;
                    float b0 = sbp[a], b1 = sbp[a + 1];
                    int i_lo = it0 + tg, i_hi = i_lo + 8;
                    *(float2*)&g_logits[(size_t)(base + i_lo) * 32 + a] =
                        make_float2(d[nt][0] + b0, d[nt][1] + b1);
                    *(float2*)&g_logits[(size_t)(base + i_hi) * 32 + a] =
                        make_float2(d[nt][2] + b0, d[nt][3] + b1);
                }
            }
            // ---- v_out 1xTF32: 12 row-tiles over warps 8-15
            {
                int ntile = (w2 < 4) ? 2 : 1;
                #pragma unroll
                for (int t = 0; t < 2; t++) {
                    if (t >= ntile) break;
                    int rt = (w2 < 4) ? (w2 * 2 + t) : (8 + (w2 - 4));
                    #pragma unroll
                    for (int nt = 0; nt < 4; nt++)
                        #pragma unroll
                        for (int u = 0; u < 4; u++) dv[t][nt][u] = 0.f;
                    #pragma unroll
                    for (int kk = 0; kk < 4; kk++) {
                        int kb = kk * 8;
                        uint a0 = tf32c(vht[(kb + tq) * 193 + rt * 16 + tg]);
                        uint a1 = tf32c(vht[(kb + tq) * 193 + rt * 16 + tg + 8]);
                        uint a2 = tf32c(vht[(kb + tq + 4) * 193 + rt * 16 + tg]);
                        uint a3 = tf32c(vht[(kb + tq + 4) * 193 + rt * 16 + tg + 8]);
                        #pragma unroll
                        for (int nt = 0; nt < 4; nt++) {
                            uint b0 = __float_as_uint(wvm[(nt * 8 + tg) * 36 + kb + tq]);
                            uint b1 = __float_as_uint(wvm[(nt * 8 + tg) * 36 + kb + tq + 4]);
                            MMA_TF32(dv[t][nt], a0, a1, a2, a3, b0, b1);
                        }
                    }
                }
            }
        }
        __syncthreads();   // all xs/vnp/vht readers done

        if (warp < 8) {
            int itile = (warp & 3) * 16, n0base = (warp >> 2) * 64;
            #pragma unroll
            for (int nt = 0; nt < 8; nt++) {
                int o = n0base + nt * 8 + 2 * tq;
                int i_lo = itile + tg, i_hi = i_lo + 8;
                xs[o * 68 + i_lo]       = sg[nt][0];
                xs[(o + 1) * 68 + i_lo] = sg[nt][1];
                xs[o * 68 + i_hi]       = sg[nt][2];
                xs[(o + 1) * 68 + i_hi] = sg[nt][3];
            }
        }
        __syncthreads();   // sig visible

        if (warp < 4) {
            // ---- gate 1xTF32: warp = 16i x 32m
            int itile = warp * 16;
            float d[4][4] = {};
            #pragma unroll
            for (int kk = 0; kk < 16; kk++) {
                int kb = kk * 8;
                uint a0 = tf32c(xs[(kb + tq) * 68 + itile + tg]);
                uint a1 = tf32c(xs[(kb + tq) * 68 + itile + tg + 8]);
                uint a2 = tf32c(xs[(kb + tq + 4) * 68 + itile + tg]);
                uint a3 = tf32c(xs[(kb + tq + 4) * 68 + itile + tg + 8]);
                #pragma unroll
                for (int nt = 0; nt < 4; nt++) {
                    uint b0 = __float_as_uint(wsvt[(kb + tq) * 36 + nt * 8 + tg]);
                    uint b1 = __float_as_uint(wsvt[(kb + tq + 4) * 36 + nt * 8 + tg]);
                    MMA_TF32(d[nt], a0, a1, a2, a3, b0, b1);
                }
            }
            #pragma unroll
            for (int nt = 0; nt < 4; nt++) {
                int m = nt * 8 + 2 * tq;
                float b0 = svb[m], b1 = svb[m + 1];
                int i_lo = itile + tg, i_hi = i_lo + 8;
                gsb[i_lo * 33 + m]     = sigf(d[nt][0] + b0);
                gsb[i_lo * 33 + m + 1] = sigf(d[nt][1] + b1);
                gsb[i_hi * 33 + m]     = sigf(d[nt][2] + b0);
                gsb[i_hi * 33 + m + 1] = sigf(d[nt][3] + b1);
            }
        }
        __syncthreads();   // gsb visible; sig reads complete

        if (warp >= 8) {
            int w2 = warp - 8;
            float* vstage = xs;   // reuse xs as [64][97]
            int ntile = (w2 < 4) ? 2 : 1;
            #pragma unroll
            for (int t = 0; t < 2; t++) {
                if (t >= ntile) break;
                int rt = (w2 < 4) ? (w2 * 2 + t) : (8 + (w2 - 4));
                #pragma unroll
                for (int nt = 0; nt < 4; nt++) {
                    int m = nt * 8 + 2 * tq;
                    #pragma unroll
                    for (int rr = 0; rr < 2; rr++) {
                        int row = rt * 16 + tg + rr * 8;
                        int i = row / 3, dd2 = row - i * 3;
                        float gv0 = gsb[i * 33 + m], gv1 = gsb[i * 33 + m + 1];
                        vstage[i * 97 + m * 3 + dd2]       = dv[t][nt][rr * 2]     * gv0;
                        vstage[i * 97 + (m + 1) * 3 + dd2] = dv[t][nt][rr * 2 + 1] * gv1;
                    }
                }
            }
            asm volatile("bar.sync 1, 256;" ::: "memory");
            for (int ii = 0; ii < 8; ii++) {
                int item = w2 * 8 + ii;
                size_t gb2 = (size_t)(base + item) * 224;
                #pragma unroll
                for (int q = 0; q < 3; q++) {
                    int l = lane + 32 * q;
                    int m = l / 3, d = l - m * 3;
                    int gpos = (m >> 3) * 56 + 32 + (m & 7) * 3 + d;
                    g_q[gb2 + gpos] = vstage[item * 97 + l];
                }
            }
        }
    }
}

// ---- K2a ----
__global__ void __launch_bounds__(256) k2a_stats() {
    __shared__ float redm[8 * 33], reds[8 * 33];
    int seg = blockIdx.x, c = blockIdx.y;
    int t = threadIdx.x, a = t & 31, part = t >> 5;
    float m = -3.4e38f, sum = 0.f;
    int nb = seg * 512 + part * 64;
    for (int i = 0; i < 64; i++) {
        float val = g_logits[((size_t)(nb + i) * C_DIM + c) * 32 + a];
        float nm = fmaxf(m, val);
        sum = sum * __expf(m - nm) + __expf(val - nm);
        m = nm;
    }
    redm[part * 33 + a] = m; reds[part * 33 + a] = sum;
    __syncthreads();
    if (t < 32) {
        float mm = redm[t], ss = reds[t];
        #pragma unroll
        for (int p = 1; p < 8; p++) {
            float m2 = redm[p * 33 + t], s2 = reds[p * 33 + t];
            float nm = fmaxf(mm, m2);
            ss = ss * __expf(mm - nm) + s2 * __expf(m2 - nm);
            mm = nm;
        }
        g_pm[(c * 16 + seg) * 32 + t] = mm;
        g_ps[(c * 16 + seg) * 32 + t] = ss;
    }
}

// ---- K3 ----
__global__ void __launch_bounds__(224) k3_compress(const float* __restrict__ s,
                                                   const float* __restrict__ v) {
    __shared__ float xt[32 * 226];
    __shared__ float wt[32 * 33];
    __shared__ float mloc[32], iloc[32];
    int t = threadIdx.x;
    int chunk = blockIdx.x, c = blockIdx.y;
    if (t < 32) {
        float m = -3.4e38f;
        #pragma unroll
        for (int sg2 = 0; sg2 < 16; sg2++) m = fmaxf(m, g_pm[(c * 16 + sg2) * 32 + t]);
        float sum = 0.f;
        #pragma unroll
        for (int sg2 = 0; sg2 < 16; sg2++)
            sum += g_ps[(c * 16 + sg2) * 32 + t] * __expf(g_pm[(c * 16 + sg2) * 32 + t] - m);
        mloc[t] = m; iloc[t] = 1.0f / sum;
    }
    int a0 = (t & 7) * 4, j0 = (t >> 3) * 8;
    ull acc[4][4] = {};
    for (int sub = 0; sub < 4; sub++) {
        __syncthreads();
        #pragma unroll 4
        for (int n = 0; n < 32; n++) {
            int item = (chunk * 128 + sub * 32 + n) * C_DIM + c;
            xt[n * 226 + t] = (t < 128) ? s[(size_t)item * 128 + t]
                                        : v[(size_t)item * 96 + (t - 128)];
        }
        for (int idx = t; idx < 1024; idx += 224) {
            int n = idx >> 5, a = idx & 31;
            int item = (chunk * 128 + sub * 32 + n) * C_DIM + c;
            wt[n * 33 + a] = __expf(g_logits[(size_t)item * 32 + a] - mloc[a]) * iloc[a];
        }
        __syncthreads();
        #pragma unroll 4
        for (int n = 0; n < 32; n++) {
            ull wpk[4];
            #pragma unroll
            for (int u = 0; u < 4; u++) wpk[u] = packx2(wt[n * 33 + a0 + u]);
            const ull* x2 = (const ull*)(xt + n * 226 + j0);
            #pragma unroll
            for (int vv = 0; vv < 4; vv++) {
                ull xp = x2[vv];
                FMA2(acc[0][vv], wpk[0], xp);
                FMA2(acc[1][vv], wpk[1], xp);
                FMA2(acc[2][vv], wpk[2], xp);
                FMA2(acc[3][vv], wpk[3], xp);
            }
        }
    }
    #pragma unroll
    for (int u = 0; u < 4; u++) {
        size_t basep = ((size_t)(chunk * C_DIM + c) * 32 + a0 + u) * 224 + j0;
        #pragma unroll
        for (int vv = 0; vv < 4; vv++) {
            float2 fr = unpk(acc[u][vv]);
            *(float2*)&g_part[basep + 2 * vv] = fr;
        }
    }
}

// ---- K4 ----
__global__ void k4_reduce() {
    int bx = blockIdx.x; int c = bx >> 5, a = bx & 31; int t = threadIdx.x;
    float sum = 0.f;
    for (int ch = 0; ch < NCHUNK; ++ch)
        sum += g_part[((size_t)(ch * C_DIM + c) * 32 + a) * 224 + t];
    g_gbuf[(a * C_DIM + c) * 224 + t] = sum;
}

// ---- K5 ----
__global__ void k5_globals(
    const float* __restrict__ k_wh, const float* __restrict__ k_ws_w, const float* __restrict__ k_ws_b,
    const float* __restrict__ k_wv, const float* __restrict__ k_wsv_w, const float* __restrict__ k_wsv_b,
    const float* __restrict__ p_wh, const float* __restrict__ p_ws_w, const float* __restrict__ p_ws_b,
    const float* __restrict__ p_wv, const float* __restrict__ p_wsv_w, const float* __restrict__ p_wsv_b) {
    __shared__ float wx[8][608];
    int tid = threadIdx.x, warp = tid >> 5, lane = tid & 31;
    int w = blockIdx.x * 8 + warp;
    int which = w >> 9, item = w & 511;
    const float* wh   = which ? p_wh    : k_wh;
    const float* wsw  = which ? p_ws_w  : k_ws_w;
    const float* wsb  = which ? p_ws_b  : k_ws_b;
    const float* wv   = which ? p_wv    : k_wv;
    const float* wsvw = which ? p_wsv_w : k_wsv_w;
    const float* wsvb = which ? p_wsv_b : k_wsv_b;
    float* x = wx[warp]; float* vhsl = x + 224; float* vns = x + 320; float* sig = x + 480;
    const float* gp = &g_gbuf[item * 224];
    #pragma unroll
    for (int k = 0; k < 7; k++) x[lane + 32 * k] = gp[lane + 32 * k];
    __syncwarp();
    float a0 = 0.f, a1 = 0.f, a2 = 0.f;
    #pragma unroll
    for (int i = 0; i < 32; i++) {
        float ww = __ldg(&wh[lane * 32 + i]);
        a0 = fmaf(x[128 + i * 3 + 0], ww, a0);
        a1 = fmaf(x[128 + i * 3 + 1], ww, a1);
        a2 = fmaf(x[128 + i * 3 + 2], ww, a2);
    }
    vhsl[lane] = a0; vhsl[32 + lane] = a1; vhsl[64 + lane] = a2;
    vns[lane] = sqrtf(fmaxf(a0 * a0 + a1 * a1 + a2 * a2, 1e-8f));
    __syncwarp();
    float so[4];
    #pragma unroll
    for (int k = 0; k < 4; k++) {
        int o = lane + 32 * k;
        float acc = __ldg(&wsb[o]);
        const float* wr = &wsw[o * 160];
        #pragma unroll
        for (int j = 0; j < 128; j++) acc = fmaf(x[j], __ldg(&wr[j]), acc);
        #pragma unroll
        for (int j = 0; j < 32; j++) acc = fmaf(vns[j], __ldg(&wr[128 + j]), acc);
        so[k] = acc;
        sig[o] = sigf(acc);
    }
    __syncwarp();
    float g = __ldg(&wsvb[lane]);
    #pragma unroll
    for (int j = 0; j < 128; j++) g = fmaf(sig[j], __ldg(&wsvw[lane * 128 + j]), g);
    float gs = sigf(g);
    float* outp = which ? g_ve : g_ke;
    int a = item >> 4, cc = item & 15;
    size_t ob = ((size_t)cc * 32 + a) * 224;
    int h = lane >> 3;
    int vpos = h * 56 + 32 + (lane & 7) * 3;
    #pragma unroll
    for (int d = 0; d < 3; d++) {
        float vo = 0.f;
        #pragma unroll
        for (int hh = 0; hh < 32; hh++) vo = fmaf(vhsl[d * 32 + hh], __ldg(&wv[lane * 32 + hh]), vo);
        outp[ob + vpos + d] = vo * gs;
    }
    #pragma unroll
    for (int k = 0; k < 4; k++) { int o = lane + 32 * k; outp[ob + k * 56 + lane] = so[k] * sig[o]; }
}

// ============================================================
// KB: attention via tf32 mma. 32 items x 1 channel, 256 threads.
// ============================================================
__global__ void __launch_bounds__(256) kb_attn(float* __restrict__ out) {
    extern __shared__ float sm[];
    float* qe  = sm;            // [224][33] tf32 bits
    float* keT = sm + 7392;     // [224][34] tf32 bits
    float* ve  = sm + 15008;    // [32][226] fp32
    float* al  = sm + 22240;    // [32][133] fp32
    int tid = threadIdx.x;
    int c = blockIdx.y;
    int nb = blockIdx.x * 32;

    for (int idx = tid; idx < 32 * 224; idx += 256) {
        int i = idx / 224, pos = idx - i * 224;
        size_t git = (size_t)(nb + i) * 16 + c;
        qe[pos * 33 + i] = __uint_as_float(tf32c(g_q[git * 224 + pos]));
    }
    for (int idx = tid; idx < 32 * 224; idx += 256) {
        int r = idx / 224, pos = idx - r * 224;
        size_t gb = ((size_t)c * 32 + r) * 224 + pos;
        keT[pos * 34 + r] = __uint_as_float(tf32c(g_ke[gb]));
        ve[r * 226 + pos] = g_ve[gb];
    }
    __syncthreads();

    int warp = tid >> 5, lane = tid & 31;
    int h = warp >> 1, mt = warp & 1;
    int it0 = mt * 16;
    int tg = lane >> 2, tq = lane & 3;

    {
        float d[4][4] = {};
        #pragma unroll
        for (int kk = 0; kk < 7; kk++) {
            int kbase = h * 56 + kk * 8;
            uint a0 = __float_as_uint(qe[(kbase + tq) * 33 + it0 + tg]);
            uint a1 = __float_as_uint(qe[(kbase + tq) * 33 + it0 + tg + 8]);
            uint a2 = __float_as_uint(qe[(kbase + tq + 4) * 33 + it0 + tg]);
            uint a3 = __float_as_uint(qe[(kbase + tq + 4) * 33 + it0 + tg + 8]);
            #pragma unroll
            for (int nt = 0; nt < 4; nt++) {
                uint b0 = __float_as_uint(keT[(kbase + tq) * 34 + nt * 8 + tg]);
                uint b1 = __float_as_uint(keT[(kbase + tq + 4) * 34 + nt * 8 + tg]);
                MMA_TF32(d[nt], a0, a1, a2, a3, b0, b1);
            }
        }
        #pragma unroll
        for (int nt = 0; nt < 4; nt++) {
            int a = nt * 8 + 2 * tq;
            int i_lo = it0 + tg, i_hi = i_lo + 8;
            al[i_lo * 133 + h * 33 + a]     = d[nt][0] * ESCALE;
            al[i_lo * 133 + h * 33 + a + 1] = d[nt][1] * ESCALE;
            al[i_hi * 133 + h * 33 + a]     = d[nt][2] * ESCALE;
            al[i_hi * 133 + h * 33 + a + 1] = d[nt][3] * ESCALE;
        }
    }
    __syncthreads();

    if (tid < 128) {
        int i = tid >> 2, h2 = tid & 3;
        float* row = &al[i * 133 + h2 * 33];
        float ev[32], mx = -3.4e38f;
        #pragma unroll
        for (int k = 0; k < 32; k++) { ev[k] = row[k]; mx = fmaxf(mx, ev[k]); }
        float sum = 0.f;
        #pragma unroll
        for (int k = 0; k < 32; k++) { ev[k] = __expf(ev[k] - mx); sum += ev[k]; }
        float inv = 1.0f / sum;
        #pragma unroll
        for (int k = 0; k < 32; k++) row[k] = ev[k] * inv;
    }
    __syncthreads();

    {
        float d2[7][4] = {};
        #pragma unroll
        for (int kk = 0; kk < 4; kk++) {
            int kb = kk * 8;
            uint a0 = tf32c(al[(it0 + tg) * 133 + h * 33 + kb + tq]);
            uint a1 = tf32c(al[(it0 + tg + 8) * 133 + h * 33 + kb + tq]);
            uint a2 = tf32c(al[(it0 + tg) * 133 + h * 33 + kb + tq + 4]);
            uint a3 = tf32c(al[(it0 + tg + 8) * 133 + h * 33 + kb + tq + 4]);
            #pragma unroll
            for (int nt = 0; nt < 7; nt++) {
                uint b0 = tf32c(ve[(kb + tq) * 226 + h * 56 + nt * 8 + tg]);
                uint b1 = tf32c(ve[(kb + tq + 4) * 226 + h * 56 + nt * 8 + tg]);
                MMA_TF32(d2[nt], a0, a1, a2, a3, b0, b1);
            }
        }
        #pragma unroll
        for (int nt = 0; nt < 7; nt++) {
            int j = nt * 8 + 2 * tq;
            int i_lo = it0 + tg, i_hi = i_lo + 8;
            size_t g_lo = (size_t)(nb + i_lo) * 16 + c;
            size_t g_hi = (size_t)(nb + i_hi) * 16 + c;
            if (j < 32) {
                *(float2*)&out[g_lo * 128 + h * 32 + j] = make_float2(d2[nt][0], d2[nt][1]);
                *(float2*)&out[g_hi * 128 + h * 32 + j] = make_float2(d2[nt][2], d2[nt][3]);
            } else {
                *(float2*)&out[(size_t)NC_ITEMS * 128 + g_lo * 96 + h * 24 + j - 32] =
                    make_float2(d2[nt][0], d2[nt][1]);
                *(float2*)&out[(size_t)NC_ITEMS * 128 + g_hi * 96 + h * 24 + j - 32] =
                    make_float2(d2[nt][2], d2[nt][3]);
            }
        }
    }
}

// ============================================================
extern "C" void kernel_launch(void* const* d_in, const int* in_sizes, int n_in,
                              void* d_out, int out_size) {
    (void)in_sizes; (void)n_in; (void)out_size;
    const float* s       = (const float*)d_in[0];
    const float* v       = (const float*)d_in[1];
    const float* wp_wh   = (const float*)d_in[2];
    const float* wp_ws_w = (const float*)d_in[3];
    const float* wp_ws_b = (const float*)d_in[4];
    const float* q_wh    = (const float*)d_in[5];
    const float* q_ws_w  = (const float*)d_in[6];
    const float* q_ws_b  = (const float*)d_in[7];
    const float* q_wv    = (const float*)d_in[8];
    const float* q_wsv_w = (const float*)d_in[9];
    const float* q_wsv_b = (const float*)d_in[10];
    const float* k_wh    = (const float*)d_in[11];
    const float* k_ws_w  = (const float*)d_in[12];
    const float* k_ws_b  = (const float*)d_in[13];
    const float* k_wv    = (const float*)d_in[14];
    const float* k_wsv_w = (const float*)d_in[15];
    const float* k_wsv_b = (const float*)d_in[16];
    const float* vp_wh   = (const float*)d_in[17];
    const float* vp_ws_w = (const float*)d_in[18];
    const float* vp_ws_b = (const float*)d_in[19];
    const float* vp_wv   = (const float*)d_in[20];
    const float* vp_wsv_w= (const float*)d_in[21];
    const float* vp_wsv_b= (const float*)d_in[22];
    float* out = (float*)d_out;

    cudaFuncSetAttribute((const void*)ka_gvp,  cudaFuncAttributeMaxDynamicSharedMemorySize, KA_SMEMF * 4);
    cudaFuncSetAttribute((const void*)kb_attn, cudaFuncAttributeMaxDynamicSharedMemorySize, 26496 * 4);

    k0c<<<16, 256>>>(q_wsv_w);
    kz<<<1, 32>>>(0);
    kz<<<1, 32>>>(1);
    ka_gvp<<<148, 512, KA_SMEMF * 4>>>(s, v, q_wh, q_ws_w, q_ws_b, q_wv,
                                       q_wsv_b, wp_wh, wp_ws_w, wp_ws_b);   // 4th -> profiled
    k2a_stats<<<dim3(16, 16), 256>>>();
    k3_compress<<<dim3(NCHUNK, C_DIM), 224>>>(s, v);
    k4_reduce<<<512, 224>>>();
    k5_globals<<<128, 256>>>(k_wh, k_ws_w, k_ws_b, k_wv, k_wsv_w, k_wsv_b,
                             vp_wh, vp_ws_w, vp_ws_b, vp_wv, vp_wsv_w, vp_wsv_b);
    kb_attn<<<dim3(256, C_DIM), 256, 26496 * 4>>>(out);
}